// round 1
// baseline (speedup 1.0000x reference)
#include <cuda_runtime.h>
#include <cuda_bf16.h>

// Problem constants (fixed shapes per reference):
//   xs [B=32, T=512, D=1024] f32, spans [N,2] i32, batch_ids [N] i32,
//   W1 [2D=2048, H=150] f32, b1 [H], W2 [H, L=17] f32, b2 [L]
//   out [N, 17] f32
// out = relu(concat(xs[b,s0], xs[b,s1]) @ W1 + b1) @ W2 + b2

#define D_    1024
#define T_    512
#define H_    150
#define L_    17
#define K2_   (2 * D_)

#define BS 64      // spans per block
#define BK 16      // k-chunk
#define HP 160     // padded hidden (for tile + index math)
#define NT 256     // threads

// smem layout (floats):
//  phase 1: As [BK][BS] @ 0 (1024), Bs [BK][HP] @ 1024 (2560)   -> 3584
//  phase 2: hsm [BS][151] @ 0 (9664)  (aliases As/Bs after barrier)
//  always : W2s @ 9664 (2550), b2s @ 12214 (17)
#define SM_BS    1024
#define SM_W2    9664
#define SM_B2    12214
#define SM_TOTAL 12231
#define HSTRIDE  151

__global__ __launch_bounds__(NT)
void span_mlp_kernel(const float* __restrict__ xs,
                     const int*   __restrict__ spans,
                     const int*   __restrict__ bids,
                     const float* __restrict__ W1,
                     const float* __restrict__ b1,
                     const float* __restrict__ W2,
                     const float* __restrict__ b2,
                     float* __restrict__ out,
                     int N)
{
    __shared__ float sm[SM_TOTAL];
    float* As  = sm;            // [BK][BS]
    float* Bs  = sm + SM_BS;    // [BK][HP]
    float* hsm = sm;            // [BS][HSTRIDE] (phase 2, aliases As/Bs)
    float* W2s = sm + SM_W2;    // [H_*L_]
    float* b2s = sm + SM_B2;    // [L_]

    const int tid = threadIdx.x;
    const int g0  = blockIdx.x * BS;

    // Resident W2 / b2 (region does not overlap phase-1 tiles).
    for (int i = tid; i < H_ * L_; i += NT) W2s[i] = W2[i];
    if (tid < L_) b2s[tid] = b2[tid];

    // A-gather assignment: thread loads one float4 of feat for span `ls`,
    // k-quad `kq` within the BK chunk.
    const int ls = tid & (BS - 1);   // 0..63
    const int kq = tid >> 6;         // 0..3
    long base0 = 0, base1 = 0;
    {
        int g = g0 + ls;
        if (g < N) {
            int s0 = spans[2 * g + 0];
            int s1 = spans[2 * g + 1];
            int b  = bids[g];
            base0 = (long)(b * T_ + s0) * D_;
            base1 = (long)(b * T_ + s1) * D_;
        }
    }

    // Compute assignment: 16x16 threads; thread owns 4 spans x 10 hidden.
    const int tx = tid & 15;   // hidden group: h = tx + 16*j
    const int ty = tid >> 4;   // span group:  s = ty*4 + i

    float acc[4][10];
#pragma unroll
    for (int i = 0; i < 4; ++i)
#pragma unroll
        for (int j = 0; j < 10; ++j) acc[i][j] = 0.f;

    for (int k0 = 0; k0 < K2_; k0 += BK) {
        // ---- load A quad from gathered xs (global, float4, L2-resident) ----
        const int k = k0 + kq * 4;
        float4 av;
        if (k < D_) av = *(const float4*)(xs + base0 + k);
        else        av = *(const float4*)(xs + base1 + (k - D_));

        __syncthreads();   // previous iter done reading tiles

        As[(kq * 4 + 0) * BS + ls] = av.x;
        As[(kq * 4 + 1) * BS + ls] = av.y;
        As[(kq * 4 + 2) * BS + ls] = av.z;
        As[(kq * 4 + 3) * BS + ls] = av.w;

        // ---- load B tile: W1[k0..k0+15][0..149], zero-pad to 160 ----
#pragma unroll
        for (int r = 0; r < (BK * HP) / NT; ++r) {  // 10
            int idx = tid + r * NT;
            int kk  = idx / HP;
            int h   = idx - kk * HP;
            Bs[idx] = (h < H_) ? W1[(long)(k0 + kk) * H_ + h] : 0.f;
        }
        __syncthreads();

        // ---- FMA core: 16 k x (4 spans x 10 hidden) ----
#pragma unroll
        for (int kk = 0; kk < BK; ++kk) {
            float4 a4 = *(const float4*)(As + kk * BS + ty * 4);
            float av4[4] = {a4.x, a4.y, a4.z, a4.w};
            const float* bp = Bs + kk * HP + tx;
#pragma unroll
            for (int j = 0; j < 10; ++j) {
                float bv = bp[16 * j];
                acc[0][j] += av4[0] * bv;
                acc[1][j] += av4[1] * bv;
                acc[2][j] += av4[2] * bv;
                acc[3][j] += av4[3] * bv;
            }
        }
    }

    __syncthreads();   // everyone done with As/Bs before aliasing as hsm

    // ---- epilogue 1: h = relu(acc + b1) -> smem [BS][151] ----
#pragma unroll
    for (int i = 0; i < 4; ++i) {
        int s = ty * 4 + i;
#pragma unroll
        for (int j = 0; j < 10; ++j) {
            int h = tx + 16 * j;
            if (h < H_)
                hsm[s * HSTRIDE + h] = fmaxf(acc[i][j] + __ldg(&b1[h]), 0.f);
        }
    }
    __syncthreads();

    // ---- epilogue 2 (GEMM2): out[64][17] = hsm[64][150] @ W2s + b2 ----
    for (int o = tid; o < BS * L_; o += NT) {
        int s = o / L_;
        int l = o - s * L_;
        float sum = b2s[l];
        const float* hp = hsm + s * HSTRIDE;
#pragma unroll 5
        for (int kx = 0; kx < H_; ++kx)
            sum += hp[kx] * W2s[kx * L_ + l];
        int g = g0 + s;
        if (g < N) out[(long)g * L_ + l] = sum;
    }
}

extern "C" void kernel_launch(void* const* d_in, const int* in_sizes, int n_in,
                              void* d_out, int out_size)
{
    const float* xs    = (const float*)d_in[0];
    const int*   spans = (const int*)  d_in[1];
    const int*   bids  = (const int*)  d_in[2];
    const float* W1    = (const float*)d_in[3];
    const float* b1    = (const float*)d_in[4];
    const float* W2    = (const float*)d_in[5];
    const float* b2    = (const float*)d_in[6];
    float* out = (float*)d_out;

    const int N = in_sizes[2];                 // batch_ids element count
    const int grid = (N + BS - 1) / BS;

    span_mlp_kernel<<<grid, NT>>>(xs, spans, bids, W1, b1, W2, b2, out, N);
}

// round 3
// speedup vs baseline: 2.4825x; 2.4825x over previous
#include <cuda_runtime.h>
#include <cuda_bf16.h>
#include <cstdint>

// ============================================================================
// out = relu(concat(xs[b,s0], xs[b,s1]) @ W1 + b1) @ W2 + b2
//   xs [32,512,1024] f32, spans [N,2] i32, batch_ids [N] i32,
//   W1 [2048,150] f32, b1[150], W2 [150,17] f32, b2[17], out [N,17] f32
//
// GEMM1 on mma.sync.m16n8k16 bf16 (sm_80 PTX -> works on plain sm_103 target),
// 3-pass hi/lo split for ~fp32 accuracy. GEMM2 fused in fragment domain.
// ============================================================================

#define T_SEQ 512
#define D_    1024
#define H_    150
#define HP_   160
#define L_    17

#define NT     256       // threads (8 warps)
#define M_CTA  128       // spans per CTA
#define BK     32        // K per tile
#define NITER  64        // 2048 / 32

// --- smem byte offsets (stage-relative) ---
#define OFF_AHI  0
#define OFF_ALO  10240      // 128 rows x 80B
#define OFF_BHI  20480
#define OFF_BLO  33280      // 160 rows x 80B
#define STAGE    46080
// --- absolute ---
#define OFF_W2S  92160      // 160*17 f32 (zero-padded rows >=150)
#define OFF_B1S  103040     // 160 f32
#define OFF_B2S  103680     // 17 f32
#define SMEM_TOTAL 103760

// prep output: W1 split into bf16 hi/lo, tile-packed [64][160][32]
__device__ __align__(16) __nv_bfloat16 g_Bhi[NITER * HP_ * BK];
__device__ __align__(16) __nv_bfloat16 g_Blo[NITER * HP_ * BK];

__device__ __forceinline__ uint32_t smem_u32(const void* p) {
    uint32_t a;
    asm("{ .reg .u64 t; cvta.to.shared.u64 t, %1; cvt.u32.u64 %0, t; }"
        : "=r"(a) : "l"(p));
    return a;
}

#define LDSM4(r0, r1, r2, r3, addr)                                          \
    asm volatile("ldmatrix.sync.aligned.m8n8.x4.shared.b16 "                 \
                 "{%0,%1,%2,%3}, [%4];"                                      \
                 : "=r"(r0), "=r"(r1), "=r"(r2), "=r"(r3) : "r"(addr))

#define MMA16816(d, a0, a1, a2, a3, b0, b1)                                  \
    asm volatile("mma.sync.aligned.m16n8k16.row.col.f32.bf16.bf16.f32 "      \
                 "{%0,%1,%2,%3}, {%4,%5,%6,%7}, {%8,%9}, {%0,%1,%2,%3};"     \
                 : "+f"((d)[0]), "+f"((d)[1]), "+f"((d)[2]), "+f"((d)[3])    \
                 : "r"(a0), "r"(a1), "r"(a2), "r"(a3), "r"(b0), "r"(b1))

// ---------------------------------------------------------------------------
// Prep: W1 [2048,150] f32 -> hi/lo bf16 tiles [t][n][kk], n padded to 160.
// ---------------------------------------------------------------------------
__global__ void prep_w1_kernel(const float* __restrict__ W1) {
    int idx = blockIdx.x * 256 + threadIdx.x;
    if (idx >= NITER * HP_ * BK) return;
    int t   = idx / (HP_ * BK);
    int rem = idx - t * (HP_ * BK);
    int kk  = rem / HP_;
    int n   = rem - kk * HP_;
    float v = (n < H_) ? W1[(long)(t * BK + kk) * H_ + n] : 0.f;
    __nv_bfloat16 hi = __float2bfloat16(v);
    __nv_bfloat16 lo = __float2bfloat16(v - __bfloat162float(hi));
    int o = (t * HP_ + n) * BK + kk;
    g_Bhi[o] = hi;
    g_Blo[o] = lo;
}

// ---------------------------------------------------------------------------
__global__ __launch_bounds__(NT)
void span_mlp_hmma_kernel(const float* __restrict__ xs,
                          const int*   __restrict__ spans,
                          const int*   __restrict__ bids,
                          const float* __restrict__ b1,
                          const float* __restrict__ W2,
                          const float* __restrict__ b2,
                          float* __restrict__ out,
                          int N)
{
    extern __shared__ __align__(128) char smem[];
    const uint32_t sbase = smem_u32(smem);
    const int tid  = threadIdx.x;
    const int lane = tid & 31;
    const int wid  = tid >> 5;
    const int g0   = blockIdx.x * M_CTA;

    float* W2s = (float*)(smem + OFF_W2S);
    float* b1s = (float*)(smem + OFF_B1S);
    float* b2s = (float*)(smem + OFF_B2S);
    for (int i = tid; i < HP_ * L_; i += NT) {
        int r = i / L_;
        W2s[i] = (r < H_) ? W2[i] : 0.f;
    }
    if (tid < HP_) b1s[tid] = (tid < H_) ? b1[tid] : 0.f;
    if (tid < L_)  b2s[tid] = b2[tid];

    // ---- A gather setup: thread loads row=tid>>1, half=tid&1 (16 floats) ----
    const int arow = tid >> 1;
    const int half = tid & 1;
    long base0 = 0, base1 = 0;
    {
        int g = g0 + arow;
        if (g < N) {
            int s0 = spans[2 * g + 0];
            int s1 = spans[2 * g + 1];
            int b  = bids[g];
            base0 = (long)(b * T_SEQ + s0) * D_;
            base1 = (long)(b * T_SEQ + s1) * D_;
        }
    }

    // ldmatrix per-lane row offsets
    const uint32_t rowOffA = (uint32_t)((lane & 15) * 80 + (lane >> 4) * 16
                                        + wid * 16 * 80);
    const uint32_t rowOffB = (uint32_t)((lane & 7) * 80 + (lane >> 3) * 16);

    float acc[20][4];
#pragma unroll
    for (int j = 0; j < 20; ++j)
#pragma unroll
        for (int q = 0; q < 4; ++q) acc[j][q] = 0.f;

    const uint4* bhiG = (const uint4*)g_Bhi;   // 640 uint4 per tile
    const uint4* bloG = (const uint4*)g_Blo;

    // ---- helper lambdas (inlined) ----
    auto ld_tile_regs = [&](int t, float4 pa[4], uint4 pb[5]) {
        const int k = t * BK;
        const float* src = (k < D_) ? (xs + base0 + k) : (xs + base1 + (k - D_));
        src += half * 16;
#pragma unroll
        for (int i = 0; i < 4; ++i) pa[i] = __ldg((const float4*)src + i);
#pragma unroll
        for (int r = 0; r < 5; ++r) {
            int c = tid + r * NT;            // 0..1279
            pb[r] = (c < 640) ? __ldg(&bhiG[t * 640 + c])
                              : __ldg(&bloG[t * 640 + (c - 640)]);
        }
    };
    auto st_tile = [&](int t, const float4 pa[4], const uint4 pb[5]) {
        char* ns = smem + (t & 1) * STAGE;
        char* pA = ns + arow * 80 + half * 32;
#pragma unroll
        for (int i = 0; i < 4; ++i) {
            float4 v = pa[i];
            __nv_bfloat162 h01 = __float22bfloat162_rn(make_float2(v.x, v.y));
            __nv_bfloat162 h23 = __float22bfloat162_rn(make_float2(v.z, v.w));
            float2 f01 = __bfloat1622float2(h01);
            float2 f23 = __bfloat1622float2(h23);
            __nv_bfloat162 l01 = __float22bfloat162_rn(make_float2(v.x - f01.x, v.y - f01.y));
            __nv_bfloat162 l23 = __float22bfloat162_rn(make_float2(v.z - f23.x, v.w - f23.y));
            uint2 hv = make_uint2(*(uint32_t*)&h01, *(uint32_t*)&h23);
            uint2 lv = make_uint2(*(uint32_t*)&l01, *(uint32_t*)&l23);
            *(uint2*)(pA + OFF_AHI + i * 8) = hv;
            *(uint2*)(pA + OFF_ALO + i * 8) = lv;
        }
#pragma unroll
        for (int r = 0; r < 5; ++r) {
            int c = tid + r * NT;
            int rem = (c < 640) ? c : c - 640;
            int off = (c < 640) ? OFF_BHI : OFF_BLO;
            int n = rem >> 2, q = rem & 3;
            *(uint4*)(ns + off + n * 80 + q * 16) = pb[r];
        }
    };

    // ---- prologue: fill stage 0 ----
    {
        float4 pa[4]; uint4 pb[5];
        ld_tile_regs(0, pa, pb);
        st_tile(0, pa, pb);
    }
    __syncthreads();

    // ---- main loop ----
#pragma unroll 1
    for (int t = 0; t < NITER; ++t) {
        float4 pa[4]; uint4 pb[5];
        if (t + 1 < NITER) ld_tile_regs(t + 1, pa, pb);

        const uint32_t st = sbase + (uint32_t)((t & 1) * STAGE);
        const uint32_t aHi = st + OFF_AHI + rowOffA;
        const uint32_t aLo = st + OFF_ALO + rowOffA;
        const uint32_t bHi = st + OFF_BHI + rowOffB;
        const uint32_t bLo = st + OFF_BLO + rowOffB;

        uint32_t ah[8], al[8];
        LDSM4(ah[0], ah[1], ah[2], ah[3], aHi);
        LDSM4(ah[4], ah[5], ah[6], ah[7], aHi + 32);
        LDSM4(al[0], al[1], al[2], al[3], aLo);
        LDSM4(al[4], al[5], al[6], al[7], aLo + 32);

#pragma unroll
        for (int j = 0; j < 20; ++j) {
            uint32_t bh0, bh1, bh2, bh3, bl0, bl1, bl2, bl3;
            LDSM4(bh0, bh1, bh2, bh3, bHi + j * 640);
            MMA16816(acc[j], ah[0], ah[1], ah[2], ah[3], bh0, bh1);
            MMA16816(acc[j], ah[4], ah[5], ah[6], ah[7], bh2, bh3);
            MMA16816(acc[j], al[0], al[1], al[2], al[3], bh0, bh1);
            MMA16816(acc[j], al[4], al[5], al[6], al[7], bh2, bh3);
            LDSM4(bl0, bl1, bl2, bl3, bLo + j * 640);
            MMA16816(acc[j], ah[0], ah[1], ah[2], ah[3], bl0, bl1);
            MMA16816(acc[j], ah[4], ah[5], ah[6], ah[7], bl2, bl3);
        }

        __syncthreads();
        if (t + 1 < NITER) st_tile(t + 1, pa, pb);
        __syncthreads();
    }

    // ---- fused epilogue in fragment domain ----
    // thread owns rows rA = wid*16 + lane/4, rB = rA + 8;
    // cols c0 = 8j + (lane%4)*2, c1 = c0+1 for j in [0,20)
    float pOutA[L_], pOutB[L_];
#pragma unroll
    for (int l = 0; l < L_; ++l) { pOutA[l] = 0.f; pOutB[l] = 0.f; }

#pragma unroll
    for (int j = 0; j < 20; ++j) {
        int c0 = 8 * j + (lane & 3) * 2;
        int c1 = c0 + 1;
        float hA0 = fmaxf(acc[j][0] + b1s[c0], 0.f);
        float hA1 = fmaxf(acc[j][1] + b1s[c1], 0.f);
        float hB0 = fmaxf(acc[j][2] + b1s[c0], 0.f);
        float hB1 = fmaxf(acc[j][3] + b1s[c1], 0.f);
        const float* w0 = W2s + c0 * L_;
        const float* w1 = W2s + c1 * L_;
#pragma unroll
        for (int l = 0; l < L_; ++l) {
            float x0 = w0[l], x1 = w1[l];
            pOutA[l] += hA0 * x0 + hA1 * x1;
            pOutB[l] += hB0 * x0 + hB1 * x1;
        }
    }
    // reduce across the 4 lanes of each quad
#pragma unroll
    for (int l = 0; l < L_; ++l) {
        pOutA[l] += __shfl_xor_sync(0xFFFFFFFF, pOutA[l], 1);
        pOutA[l] += __shfl_xor_sync(0xFFFFFFFF, pOutA[l], 2);
        pOutB[l] += __shfl_xor_sync(0xFFFFFFFF, pOutB[l], 1);
        pOutB[l] += __shfl_xor_sync(0xFFFFFFFF, pOutB[l], 2);
    }
    {
        int rA = g0 + wid * 16 + (lane >> 2);
        int rB = rA + 8;
#pragma unroll
        for (int l = 0; l < L_; ++l) {
            if ((l & 3) == (lane & 3)) {   // spread stores across the quad
                if (rA < N) out[(long)rA * L_ + l] = pOutA[l] + b2s[l];
                if (rB < N) out[(long)rB * L_ + l] = pOutB[l] + b2s[l];
            }
        }
    }
}

// ---------------------------------------------------------------------------
extern "C" void kernel_launch(void* const* d_in, const int* in_sizes, int n_in,
                              void* d_out, int out_size)
{
    const float* xs    = (const float*)d_in[0];
    const int*   spans = (const int*)  d_in[1];
    const int*   bids  = (const int*)  d_in[2];
    const float* W1    = (const float*)d_in[3];
    const float* b1    = (const float*)d_in[4];
    const float* W2    = (const float*)d_in[5];
    const float* b2    = (const float*)d_in[6];
    float* out = (float*)d_out;
    const int N = in_sizes[2];

    static bool attr_set = false;  // setting an attribute is idempotent + capture-safe
    cudaFuncSetAttribute(span_mlp_hmma_kernel,
                         cudaFuncAttributeMaxDynamicSharedMemorySize, SMEM_TOTAL);
    (void)attr_set;

    int prep_items = NITER * HP_ * BK;
    prep_w1_kernel<<<(prep_items + 255) / 256, 256>>>(W1);

    int grid = (N + M_CTA - 1) / M_CTA;
    span_mlp_hmma_kernel<<<grid, NT, SMEM_TOTAL>>>(xs, spans, bids, b1, W2, b2, out, N);
}

// round 4
// speedup vs baseline: 3.1706x; 1.2772x over previous
#include <cuda_runtime.h>
#include <cuda_fp16.h>
#include <cstdint>

// ============================================================================
// out = relu(concat(xs[b,s0], xs[b,s1]) @ W1 + b1) @ W2 + b2
//   xs [32,512,1024] f32, spans [N,2] i32, batch_ids [N] i32,
//   W1 [2048,150] f32, b1[150], W2 [150,17] f32, b2[17], out [N,17] f32
//
// GEMM1: mma.sync.m16n8k16 fp16. A = fp16(xs) single; B = fp16 hi/lo split
// (2 passes; dropped term ~2^-11/sqrt(3) ~ 2.8e-4 rel, under 1e-3 gate).
// Prep kernels pre-convert xs and pre-pack W1 tiles; main loop is pure
// cp.async (3-stage) + ldmatrix + HMMA, one syncthreads per K-tile.
// GEMM2 fused in the accumulator fragment domain.
// ============================================================================

#define T_SEQ 512
#define D_    1024
#define H_    150
#define HP_   160
#define L_    17

#define NT     256       // 8 warps
#define M_CTA  256       // spans per CTA (2 m-tiles of 16 per warp)
#define BK     32        // K per tile
#define NITER  64        // 2048/32

// stage-relative smem offsets (bytes); rows are 80B (40 halfs, k<32 valid)
#define OFF_A    0              // 256 rows x 80B = 20480
#define OFF_BH   20480          // 160 rows x 80B = 12800
#define OFF_BL   33280          // 160 rows x 80B = 12800
#define STAGE    46080
#define NSTG     3
// absolute
#define OFF_W2S  (NSTG * STAGE)           // 160*17 f32
#define OFF_B1S  (OFF_W2S + 10880)        // 160 f32
#define OFF_B2S  (OFF_B1S + 640)          // 17 f32
#define SMEM_TOTAL (OFF_B2S + 80)         // ~149.9 KB

// prep outputs
__device__ __align__(16) __half g_xsh[32 * 512 * 1024];           // 32 MB
__device__ __align__(16) __half g_Bpk[NITER * 2 * HP_ * 40];      // 1.6 MB

__device__ __forceinline__ uint32_t smem_u32(const void* p) {
    uint32_t a;
    asm("{ .reg .u64 t; cvta.to.shared.u64 t, %1; cvt.u32.u64 %0, t; }"
        : "=r"(a) : "l"(p));
    return a;
}

#define LDSM4(r0, r1, r2, r3, addr)                                          \
    asm volatile("ldmatrix.sync.aligned.m8n8.x4.shared.b16 "                 \
                 "{%0,%1,%2,%3}, [%4];"                                      \
                 : "=r"(r0), "=r"(r1), "=r"(r2), "=r"(r3) : "r"(addr))

#define MMA16816(d, a0, a1, a2, a3, b0, b1)                                  \
    asm volatile("mma.sync.aligned.m16n8k16.row.col.f32.f16.f16.f32 "        \
                 "{%0,%1,%2,%3}, {%4,%5,%6,%7}, {%8,%9}, {%0,%1,%2,%3};"     \
                 : "+f"((d)[0]), "+f"((d)[1]), "+f"((d)[2]), "+f"((d)[3])    \
                 : "r"(a0), "r"(a1), "r"(a2), "r"(a3), "r"(b0), "r"(b1))

#define CP16(dst, src)                                                        \
    asm volatile("cp.async.cg.shared.global [%0], [%1], 16;"                  \
                 :: "r"(dst), "l"(src))
#define CP_COMMIT() asm volatile("cp.async.commit_group;" ::: "memory")
#define CP_WAIT1()  asm volatile("cp.async.wait_group 1;" ::: "memory")

// ---------------------------------------------------------------------------
// Prep 1: xs f32 -> fp16 (8 floats / thread)
// ---------------------------------------------------------------------------
__global__ void prep_xs_kernel(const float* __restrict__ xs) {
    long i8 = (long)(blockIdx.x * 256 + threadIdx.x) * 8;
    float4 v0 = *(const float4*)(xs + i8);
    float4 v1 = *(const float4*)(xs + i8 + 4);
    __half2 h[4];
    h[0] = __float22half2_rn(make_float2(v0.x, v0.y));
    h[1] = __float22half2_rn(make_float2(v0.z, v0.w));
    h[2] = __float22half2_rn(make_float2(v1.x, v1.y));
    h[3] = __float22half2_rn(make_float2(v1.z, v1.w));
    *(uint4*)(g_xsh + i8) = *(uint4*)h;
}

// ---------------------------------------------------------------------------
// Prep 2: W1 [2048,150] f32 -> packed fp16 hi/lo tiles
//   layout (halfs): [t][pass][n(160)][kk(40)], kk<32 & n<150 valid else 0
// ---------------------------------------------------------------------------
__global__ void prep_w1_kernel(const float* __restrict__ W1) {
    int idx = blockIdx.x * 256 + threadIdx.x;
    if (idx >= NITER * 2 * HP_ * 40) return;
    int t    = idx / 12800;
    int rem  = idx - t * 12800;
    int pass = rem / 6400;
    int r2   = rem - pass * 6400;
    int n    = r2 / 40;
    int kk   = r2 - n * 40;
    float w = (kk < BK && n < H_) ? W1[(long)(t * BK + kk) * H_ + n] : 0.f;
    __half hi = __float2half_rn(w);
    __half v  = pass ? __float2half_rn(w - __half2float(hi)) : hi;
    g_Bpk[idx] = v;
}

// ---------------------------------------------------------------------------
__global__ __launch_bounds__(NT)
void span_mlp_hmma2_kernel(const int*   __restrict__ spans,
                           const int*   __restrict__ bids,
                           const float* __restrict__ b1,
                           const float* __restrict__ W2,
                           const float* __restrict__ b2,
                           float* __restrict__ out,
                           int N)
{
    extern __shared__ __align__(128) char smem[];
    const uint32_t sbase = smem_u32(smem);
    const int tid  = threadIdx.x;
    const int lane = tid & 31;
    const int wid  = tid >> 5;
    const int g0   = blockIdx.x * M_CTA;

    // span bases (elements into g_xsh) for this thread's A row
    long base0 = 0, base1 = 0;
    {
        int g = g0 + tid;
        if (g < N) {
            int s0 = spans[2 * g + 0];
            int s1 = spans[2 * g + 1];
            int b  = bids[g];
            base0 = (long)(b * T_SEQ + s0) * D_;
            base1 = (long)(b * T_SEQ + s1) * D_;
        }
    }

    // pipeline issue (stage = t%3): A row tid (4x16B), B 1600x16B
    auto issue_tile = [&](int t) {
        if (t < NITER) {
            const uint32_t st = sbase + (uint32_t)((t % NSTG) * STAGE);
            const int k0 = t * BK;
            const char* asrc = (const char*)(g_xsh +
                ((k0 < D_) ? base0 + k0 : base1 + (k0 - D_)));
            const uint32_t adst = st + OFF_A + tid * 80;
#pragma unroll
            for (int i = 0; i < 4; ++i) CP16(adst + i * 16, asrc + i * 16);
            const char* bsrc = (const char*)g_Bpk + (size_t)t * 25600;
            const uint32_t bdst = st + OFF_BH;
#pragma unroll
            for (int r = 0; r < 6; ++r) {
                int c = tid + r * NT;
                CP16(bdst + c * 16, bsrc + c * 16);
            }
            if (tid < 64) {
                int c = tid + 1536;
                CP16(bdst + c * 16, bsrc + c * 16);
            }
        }
        CP_COMMIT();
    };

    issue_tile(0);
    issue_tile(1);

    // resident W2 (zero-padded rows >=150), b1, b2
    float* W2s = (float*)(smem + OFF_W2S);
    float* b1s = (float*)(smem + OFF_B1S);
    float* b2s = (float*)(smem + OFF_B2S);
    for (int i = tid; i < HP_ * L_; i += NT)
        W2s[i] = (i / L_ < H_) ? W2[i] : 0.f;
    if (tid < HP_) b1s[tid] = (tid < H_) ? b1[tid] : 0.f;
    if (tid < L_)  b2s[tid] = b2[tid];

    // ldmatrix lane offsets
    const uint32_t rowA0 = (uint32_t)((wid * 32 + (lane & 15)) * 80
                                      + (lane >> 4) * 16) + OFF_A;
    const uint32_t rowA1 = rowA0 + 16 * 80;
    const uint32_t rowB  = (uint32_t)((lane & 7) * 80 + (lane >> 3) * 16) + OFF_BH;

    float acc[2][20][4];
#pragma unroll
    for (int m = 0; m < 2; ++m)
#pragma unroll
        for (int j = 0; j < 20; ++j)
#pragma unroll
            for (int q = 0; q < 4; ++q) acc[m][j][q] = 0.f;

#pragma unroll 1
    for (int t = 0; t < NITER; ++t) {
        CP_WAIT1();
        __syncthreads();
        const uint32_t st = sbase + (uint32_t)((t % NSTG) * STAGE);

        uint32_t a0[8], a1[8];
        LDSM4(a0[0], a0[1], a0[2], a0[3], st + rowA0);
        LDSM4(a0[4], a0[5], a0[6], a0[7], st + rowA0 + 32);
        LDSM4(a1[0], a1[1], a1[2], a1[3], st + rowA1);
        LDSM4(a1[4], a1[5], a1[6], a1[7], st + rowA1 + 32);

        const uint32_t bb = st + rowB;
#pragma unroll
        for (int j = 0; j < 20; ++j) {
            uint32_t h0, h1, h2, h3, l0, l1, l2, l3;
            LDSM4(h0, h1, h2, h3, bb + j * 640);
            LDSM4(l0, l1, l2, l3, bb + 12800 + j * 640);
            MMA16816(acc[0][j], a0[0], a0[1], a0[2], a0[3], h0, h1);
            MMA16816(acc[0][j], a0[4], a0[5], a0[6], a0[7], h2, h3);
            MMA16816(acc[1][j], a1[0], a1[1], a1[2], a1[3], h0, h1);
            MMA16816(acc[1][j], a1[4], a1[5], a1[6], a1[7], h2, h3);
            MMA16816(acc[0][j], a0[0], a0[1], a0[2], a0[3], l0, l1);
            MMA16816(acc[0][j], a0[4], a0[5], a0[6], a0[7], l2, l3);
            MMA16816(acc[1][j], a1[0], a1[1], a1[2], a1[3], l0, l1);
            MMA16816(acc[1][j], a1[4], a1[5], a1[6], a1[7], l2, l3);
        }

        issue_tile(t + 2);   // writes stage (t-1)%3: all warps past MMA(t-1)
    }

    // ---- fused epilogue in fragment domain ----
#pragma unroll
    for (int m = 0; m < 2; ++m) {
        float pA[L_], pB[L_];
#pragma unroll
        for (int l = 0; l < L_; ++l) { pA[l] = 0.f; pB[l] = 0.f; }
#pragma unroll
        for (int j = 0; j < 20; ++j) {
            int c0 = 8 * j + (lane & 3) * 2;
            int c1 = c0 + 1;
            float hA0 = fmaxf(acc[m][j][0] + b1s[c0], 0.f);
            float hA1 = fmaxf(acc[m][j][1] + b1s[c1], 0.f);
            float hB0 = fmaxf(acc[m][j][2] + b1s[c0], 0.f);
            float hB1 = fmaxf(acc[m][j][3] + b1s[c1], 0.f);
            const float* w0 = W2s + c0 * L_;
            const float* w1 = W2s + c1 * L_;
#pragma unroll
            for (int l = 0; l < L_; ++l) {
                float x0 = w0[l], x1 = w1[l];
                pA[l] += hA0 * x0 + hA1 * x1;
                pB[l] += hB0 * x0 + hB1 * x1;
            }
        }
#pragma unroll
        for (int l = 0; l < L_; ++l) {
            pA[l] += __shfl_xor_sync(0xFFFFFFFF, pA[l], 1);
            pA[l] += __shfl_xor_sync(0xFFFFFFFF, pA[l], 2);
            pB[l] += __shfl_xor_sync(0xFFFFFFFF, pB[l], 1);
            pB[l] += __shfl_xor_sync(0xFFFFFFFF, pB[l], 2);
        }
        int rA = g0 + wid * 32 + m * 16 + (lane >> 2);
        int rB = rA + 8;
#pragma unroll
        for (int l = 0; l < L_; ++l) {
            if ((l & 3) == (lane & 3)) {   // spread stores across the quad
                if (rA < N) out[(long)rA * L_ + l] = pA[l] + b2s[l];
                if (rB < N) out[(long)rB * L_ + l] = pB[l] + b2s[l];
            }
        }
    }
}

// ---------------------------------------------------------------------------
extern "C" void kernel_launch(void* const* d_in, const int* in_sizes, int n_in,
                              void* d_out, int out_size)
{
    const float* xs    = (const float*)d_in[0];
    const int*   spans = (const int*)  d_in[1];
    const int*   bids  = (const int*)  d_in[2];
    const float* W1    = (const float*)d_in[3];
    const float* b1    = (const float*)d_in[4];
    const float* W2    = (const float*)d_in[5];
    const float* b2    = (const float*)d_in[6];
    float* out = (float*)d_out;
    const int N = in_sizes[2];

    cudaFuncSetAttribute(span_mlp_hmma2_kernel,
                         cudaFuncAttributeMaxDynamicSharedMemorySize, SMEM_TOTAL);

    prep_xs_kernel<<<(32 * 512 * 1024) / (256 * 8), 256>>>(xs);
    int w1_items = NITER * 2 * HP_ * 40;
    prep_w1_kernel<<<(w1_items + 255) / 256, 256>>>(W1);

    int grid = (N + M_CTA - 1) / M_CTA;
    span_mlp_hmma2_kernel<<<grid, NT, SMEM_TOTAL>>>(spans, bids, b1, W2, b2, out, N);
}

// round 5
// speedup vs baseline: 4.2737x; 1.3479x over previous
#include <cuda_runtime.h>
#include <cuda_fp16.h>
#include <cstdint>

// ============================================================================
// out = relu(concat(xs[b,s0], xs[b,s1]) @ W1 + b1) @ W2 + b2
//   xs [32,512,1024] f32, spans [N,2] i32, batch_ids [N] i32,
//   W1 [2048,150] f32, b1[150], W2 [150,17] f32, b2[17], out [N,17] f32
//
// GEMM1: single-pass fp16 mma.sync.m16n8k16 (f32 accum). Measured A-rounding
// error 1.87e-4 (R4); adding B fp16 rounding -> ~2.6e-4 total, under the
// 1e-3 gate with 3.8x margin. Prep kernels pre-convert xs and W1 to fp16;
// main loop: cp.async 3-stage ring, 1 syncthreads/tile, fused GEMM2 epilogue.
// ============================================================================

#define T_SEQ 512
#define D_    1024
#define H_    150
#define HP_   160
#define L_    17

#define NT     256       // 8 warps
#define M_CTA  256       // spans per CTA (2 m-tiles of 16 per warp)
#define BK     32        // K per tile
#define NITER  64        // 2048/32

// stage-relative smem offsets (bytes); rows are 80B (40 halfs, k<32 valid)
#define OFF_A    0              // 256 rows x 80B = 20480
#define OFF_B    20480          // 160 rows x 80B = 12800
#define STAGE    33280
#define NSTG     3
// absolute
#define OFF_W2S  (NSTG * STAGE)           // 160*17 f32
#define OFF_B1S  (OFF_W2S + 10880)        // 160 f32
#define OFF_B2S  (OFF_B1S + 640)          // 17 f32
#define SMEM_TOTAL (OFF_B2S + 80)         // ~111.4 KB

// prep outputs
__device__ __align__(16) __half g_xsh[32 * 512 * 1024];      // 32 MB
__device__ __align__(16) __half g_Bpk[NITER * HP_ * 40];     // 0.8 MB

__device__ __forceinline__ uint32_t smem_u32(const void* p) {
    uint32_t a;
    asm("{ .reg .u64 t; cvta.to.shared.u64 t, %1; cvt.u32.u64 %0, t; }"
        : "=r"(a) : "l"(p));
    return a;
}

#define LDSM4(r0, r1, r2, r3, addr)                                          \
    asm volatile("ldmatrix.sync.aligned.m8n8.x4.shared.b16 "                 \
                 "{%0,%1,%2,%3}, [%4];"                                      \
                 : "=r"(r0), "=r"(r1), "=r"(r2), "=r"(r3) : "r"(addr))

#define MMA16816(d, a0, a1, a2, a3, b0, b1)                                  \
    asm volatile("mma.sync.aligned.m16n8k16.row.col.f32.f16.f16.f32 "        \
                 "{%0,%1,%2,%3}, {%4,%5,%6,%7}, {%8,%9}, {%0,%1,%2,%3};"     \
                 : "+f"((d)[0]), "+f"((d)[1]), "+f"((d)[2]), "+f"((d)[3])    \
                 : "r"(a0), "r"(a1), "r"(a2), "r"(a3), "r"(b0), "r"(b1))

#define CP16(dst, src)                                                        \
    asm volatile("cp.async.cg.shared.global [%0], [%1], 16;"                  \
                 :: "r"(dst), "l"(src))
#define CP_COMMIT() asm volatile("cp.async.commit_group;" ::: "memory")
#define CP_WAIT1()  asm volatile("cp.async.wait_group 1;" ::: "memory")

// ---------------------------------------------------------------------------
// Prep 1: xs f32 -> fp16 (8 floats / thread)
// ---------------------------------------------------------------------------
__global__ void prep_xs_kernel(const float* __restrict__ xs) {
    long i8 = (long)(blockIdx.x * 256 + threadIdx.x) * 8;
    float4 v0 = *(const float4*)(xs + i8);
    float4 v1 = *(const float4*)(xs + i8 + 4);
    __half2 h[4];
    h[0] = __float22half2_rn(make_float2(v0.x, v0.y));
    h[1] = __float22half2_rn(make_float2(v0.z, v0.w));
    h[2] = __float22half2_rn(make_float2(v1.x, v1.y));
    h[3] = __float22half2_rn(make_float2(v1.z, v1.w));
    *(uint4*)(g_xsh + i8) = *(uint4*)h;
}

// ---------------------------------------------------------------------------
// Prep 2: W1 [2048,150] f32 -> packed fp16 tiles [t][n(160)][kk(40)]
// ---------------------------------------------------------------------------
__global__ void prep_w1_kernel(const float* __restrict__ W1) {
    int idx = blockIdx.x * 256 + threadIdx.x;
    if (idx >= NITER * HP_ * 40) return;
    int t   = idx / 6400;
    int rem = idx - t * 6400;
    int n   = rem / 40;
    int kk  = rem - n * 40;
    float w = (kk < BK && n < H_) ? W1[(long)(t * BK + kk) * H_ + n] : 0.f;
    g_Bpk[idx] = __float2half_rn(w);
}

// ---------------------------------------------------------------------------
__global__ __launch_bounds__(NT)
void span_mlp_hmma3_kernel(const int*   __restrict__ spans,
                           const int*   __restrict__ bids,
                           const float* __restrict__ b1,
                           const float* __restrict__ W2,
                           const float* __restrict__ b2,
                           float* __restrict__ out,
                           int N)
{
    extern __shared__ __align__(128) char smem[];
    const uint32_t sbase = smem_u32(smem);
    const int tid  = threadIdx.x;
    const int lane = tid & 31;
    const int wid  = tid >> 5;
    const int g0   = blockIdx.x * M_CTA;

    // span bases (elements into g_xsh) for this thread's A row
    long base0 = 0, base1 = 0;
    {
        int g = g0 + tid;
        if (g < N) {
            int s0 = spans[2 * g + 0];
            int s1 = spans[2 * g + 1];
            int b  = bids[g];
            base0 = (long)(b * T_SEQ + s0) * D_;
            base1 = (long)(b * T_SEQ + s1) * D_;
        }
    }

    // pipeline issue (stage = t%3): A row tid (4x16B), B 800x16B
    auto issue_tile = [&](int t) {
        if (t < NITER) {
            const uint32_t st = sbase + (uint32_t)((t % NSTG) * STAGE);
            const int k0 = t * BK;
            const char* asrc = (const char*)(g_xsh +
                ((k0 < D_) ? base0 + k0 : base1 + (k0 - D_)));
            const uint32_t adst = st + OFF_A + tid * 80;
#pragma unroll
            for (int i = 0; i < 4; ++i) CP16(adst + i * 16, asrc + i * 16);
            const char* bsrc = (const char*)g_Bpk + (size_t)t * 12800;
            const uint32_t bdst = st + OFF_B;
#pragma unroll
            for (int r = 0; r < 3; ++r) {
                int c = tid + r * NT;            // 0..767
                CP16(bdst + c * 16, bsrc + c * 16);
            }
            if (tid < 32) {
                int c = tid + 768;
                CP16(bdst + c * 16, bsrc + c * 16);
            }
        }
        CP_COMMIT();
    };

    issue_tile(0);
    issue_tile(1);

    // resident W2 (zero-padded rows >=150), b1, b2
    float* W2s = (float*)(smem + OFF_W2S);
    float* b1s = (float*)(smem + OFF_B1S);
    float* b2s = (float*)(smem + OFF_B2S);
    for (int i = tid; i < HP_ * L_; i += NT)
        W2s[i] = (i / L_ < H_) ? W2[i] : 0.f;
    if (tid < HP_) b1s[tid] = (tid < H_) ? b1[tid] : 0.f;
    if (tid < L_)  b2s[tid] = b2[tid];

    // ldmatrix lane offsets
    const uint32_t rowA0 = (uint32_t)((wid * 32 + (lane & 15)) * 80
                                      + (lane >> 4) * 16) + OFF_A;
    const uint32_t rowA1 = rowA0 + 16 * 80;
    const uint32_t rowB  = (uint32_t)((lane & 7) * 80 + (lane >> 3) * 16) + OFF_B;

    float acc[2][20][4];
#pragma unroll
    for (int m = 0; m < 2; ++m)
#pragma unroll
        for (int j = 0; j < 20; ++j)
#pragma unroll
            for (int q = 0; q < 4; ++q) acc[m][j][q] = 0.f;

#pragma unroll 1
    for (int t = 0; t < NITER; ++t) {
        CP_WAIT1();
        __syncthreads();
        // safe to overwrite stage (t+2)%3 == (t-1)%3: all warps passed the
        // sync, so tile t-1 compute is complete everywhere.
        issue_tile(t + 2);

        const uint32_t st = sbase + (uint32_t)((t % NSTG) * STAGE);
        uint32_t a0[8], a1[8];
        LDSM4(a0[0], a0[1], a0[2], a0[3], st + rowA0);
        LDSM4(a0[4], a0[5], a0[6], a0[7], st + rowA0 + 32);
        LDSM4(a1[0], a1[1], a1[2], a1[3], st + rowA1);
        LDSM4(a1[4], a1[5], a1[6], a1[7], st + rowA1 + 32);

        const uint32_t bb = st + rowB;
#pragma unroll
        for (int j = 0; j < 20; ++j) {
            uint32_t b0, b1r, b2r, b3;
            LDSM4(b0, b1r, b2r, b3, bb + j * 640);
            MMA16816(acc[0][j], a0[0], a0[1], a0[2], a0[3], b0, b1r);
            MMA16816(acc[0][j], a0[4], a0[5], a0[6], a0[7], b2r, b3);
            MMA16816(acc[1][j], a1[0], a1[1], a1[2], a1[3], b0, b1r);
            MMA16816(acc[1][j], a1[4], a1[5], a1[6], a1[7], b2r, b3);
        }
    }

    // ---- fused epilogue in fragment domain ----
#pragma unroll
    for (int m = 0; m < 2; ++m) {
        float pA[L_], pB[L_];
#pragma unroll
        for (int l = 0; l < L_; ++l) { pA[l] = 0.f; pB[l] = 0.f; }
#pragma unroll
        for (int j = 0; j < 20; ++j) {
            int c0 = 8 * j + (lane & 3) * 2;
            int c1 = c0 + 1;
            float hA0 = fmaxf(acc[m][j][0] + b1s[c0], 0.f);
            float hA1 = fmaxf(acc[m][j][1] + b1s[c1], 0.f);
            float hB0 = fmaxf(acc[m][j][2] + b1s[c0], 0.f);
            float hB1 = fmaxf(acc[m][j][3] + b1s[c1], 0.f);
            const float* w0 = W2s + c0 * L_;
            const float* w1 = W2s + c1 * L_;
#pragma unroll
            for (int l = 0; l < L_; ++l) {
                float x0 = w0[l], x1 = w1[l];
                pA[l] += hA0 * x0 + hA1 * x1;
                pB[l] += hB0 * x0 + hB1 * x1;
            }
        }
#pragma unroll
        for (int l = 0; l < L_; ++l) {
            pA[l] += __shfl_xor_sync(0xFFFFFFFF, pA[l], 1);
            pA[l] += __shfl_xor_sync(0xFFFFFFFF, pA[l], 2);
            pB[l] += __shfl_xor_sync(0xFFFFFFFF, pB[l], 1);
            pB[l] += __shfl_xor_sync(0xFFFFFFFF, pB[l], 2);
        }
        int rA = g0 + wid * 32 + m * 16 + (lane >> 2);
        int rB = rA + 8;
#pragma unroll
        for (int l = 0; l < L_; ++l) {
            if ((l & 3) == (lane & 3)) {   // spread stores across the quad
                if (rA < N) out[(long)rA * L_ + l] = pA[l] + b2s[l];
                if (rB < N) out[(long)rB * L_ + l] = pB[l] + b2s[l];
            }
        }
    }
}

// ---------------------------------------------------------------------------
extern "C" void kernel_launch(void* const* d_in, const int* in_sizes, int n_in,
                              void* d_out, int out_size)
{
    const float* xs    = (const float*)d_in[0];
    const int*   spans = (const int*)  d_in[1];
    const int*   bids  = (const int*)  d_in[2];
    const float* W1    = (const float*)d_in[3];
    const float* b1    = (const float*)d_in[4];
    const float* W2    = (const float*)d_in[5];
    const float* b2    = (const float*)d_in[6];
    float* out = (float*)d_out;
    const int N = in_sizes[2];

    cudaFuncSetAttribute(span_mlp_hmma3_kernel,
                         cudaFuncAttributeMaxDynamicSharedMemorySize, SMEM_TOTAL);

    prep_xs_kernel<<<(32 * 512 * 1024) / (256 * 8), 256>>>(xs);
    int w1_items = NITER * HP_ * 40;
    prep_w1_kernel<<<(w1_items + 255) / 256, 256>>>(W1);

    int grid = (N + M_CTA - 1) / M_CTA;
    span_mlp_hmma3_kernel<<<grid, NT, SMEM_TOTAL>>>(spans, bids, b1, W2, b2, out, N);
}

// round 7
// speedup vs baseline: 5.7441x; 1.3441x over previous
#include <cuda_runtime.h>
#include <cuda_fp16.h>
#include <cstdint>

// ============================================================================
// out = relu(concat(xs[b,s0], xs[b,s1]) @ W1 + b1) @ W2 + b2
//   xs [32,512,1024] f32, spans [N,2] i32, batch_ids [N] i32,
//   W1 [2048,150] f32, b1[150], W2 [150,17] f32, b2[17], out [N,17] f32
//
// GEMM1: single-pass fp16 mma.sync.m16n8k16 (f32 accum), rel_err ~2.6e-4.
// R7 = R6 with the A-copy src offset fixed (asrc+16, was asrc+32):
// 2 CTAs/SM (4 warps/SMSP), M_CTA=128, one m-tile per warp.
// ============================================================================

#define T_SEQ 512
#define D_    1024
#define H_    150
#define HP_   160
#define L_    17

#define NT     256       // 8 warps
#define M_CTA  128       // spans per CTA (1 m-tile of 16 per warp)
#define BK     32        // K per tile
#define NITER  64        // 2048/32

// stage-relative smem offsets (bytes); rows are 80B (40 halfs, k<32 valid)
#define OFF_A    0              // 128 rows x 80B = 10240
#define OFF_B    10240          // 160 rows x 80B = 12800
#define STAGE    23040
#define NSTG     3
// absolute
#define OFF_W2S  (NSTG * STAGE)           // 160*17 f32
#define OFF_B1S  (OFF_W2S + 10880)        // 160 f32
#define OFF_B2S  (OFF_B1S + 640)          // 17 f32
#define SMEM_TOTAL (OFF_B2S + 80)         // ~80.7 KB

// prep outputs
__device__ __align__(16) __half g_xsh[32 * 512 * 1024];      // 32 MB
__device__ __align__(16) __half g_Bpk[NITER * HP_ * 40];     // 0.8 MB

__device__ __forceinline__ uint32_t smem_u32(const void* p) {
    uint32_t a;
    asm("{ .reg .u64 t; cvta.to.shared.u64 t, %1; cvt.u32.u64 %0, t; }"
        : "=r"(a) : "l"(p));
    return a;
}

#define LDSM4(r0, r1, r2, r3, addr)                                          \
    asm volatile("ldmatrix.sync.aligned.m8n8.x4.shared.b16 "                 \
                 "{%0,%1,%2,%3}, [%4];"                                      \
                 : "=r"(r0), "=r"(r1), "=r"(r2), "=r"(r3) : "r"(addr))

#define MMA16816(d, a0, a1, a2, a3, b0, b1)                                  \
    asm volatile("mma.sync.aligned.m16n8k16.row.col.f32.f16.f16.f32 "        \
                 "{%0,%1,%2,%3}, {%4,%5,%6,%7}, {%8,%9}, {%0,%1,%2,%3};"     \
                 : "+f"((d)[0]), "+f"((d)[1]), "+f"((d)[2]), "+f"((d)[3])    \
                 : "r"(a0), "r"(a1), "r"(a2), "r"(a3), "r"(b0), "r"(b1))

#define CP16(dst, src)                                                        \
    asm volatile("cp.async.cg.shared.global [%0], [%1], 16;"                  \
                 :: "r"(dst), "l"(src))
#define CP_COMMIT() asm volatile("cp.async.commit_group;" ::: "memory")
#define CP_WAIT1()  asm volatile("cp.async.wait_group 1;" ::: "memory")

// ---------------------------------------------------------------------------
// Prep 1: xs f32 -> fp16 (8 floats / thread)
// ---------------------------------------------------------------------------
__global__ void prep_xs_kernel(const float* __restrict__ xs) {
    long i8 = (long)(blockIdx.x * 256 + threadIdx.x) * 8;
    float4 v0 = *(const float4*)(xs + i8);
    float4 v1 = *(const float4*)(xs + i8 + 4);
    __half2 h[4];
    h[0] = __float22half2_rn(make_float2(v0.x, v0.y));
    h[1] = __float22half2_rn(make_float2(v0.z, v0.w));
    h[2] = __float22half2_rn(make_float2(v1.x, v1.y));
    h[3] = __float22half2_rn(make_float2(v1.z, v1.w));
    *(uint4*)(g_xsh + i8) = *(uint4*)h;
}

// ---------------------------------------------------------------------------
// Prep 2: W1 [2048,150] f32 -> packed fp16 tiles [t][n(160)][kk(40)]
// ---------------------------------------------------------------------------
__global__ void prep_w1_kernel(const float* __restrict__ W1) {
    int idx = blockIdx.x * 256 + threadIdx.x;
    if (idx >= NITER * HP_ * 40) return;
    int t   = idx / 6400;
    int rem = idx - t * 6400;
    int n   = rem / 40;
    int kk  = rem - n * 40;
    float w = (kk < BK && n < H_) ? W1[(long)(t * BK + kk) * H_ + n] : 0.f;
    g_Bpk[idx] = __float2half_rn(w);
}

// ---------------------------------------------------------------------------
__global__ __launch_bounds__(NT, 2)
void span_mlp_hmma4_kernel(const int*   __restrict__ spans,
                           const int*   __restrict__ bids,
                           const float* __restrict__ b1,
                           const float* __restrict__ W2,
                           const float* __restrict__ b2,
                           float* __restrict__ out,
                           int N)
{
    extern __shared__ __align__(128) char smem[];
    const uint32_t sbase = smem_u32(smem);
    const int tid  = threadIdx.x;
    const int lane = tid & 31;
    const int wid  = tid >> 5;
    const int g0   = blockIdx.x * M_CTA;

    // A loading: 2 threads per row (arow = tid>>1, half = tid&1, 32B each)
    const int arow = tid >> 1;
    const int half = tid & 1;
    long base0 = 0, base1 = 0;
    {
        int g = g0 + arow;
        if (g < N) {
            int s0 = spans[2 * g + 0];
            int s1 = spans[2 * g + 1];
            int b  = bids[g];
            base0 = (long)(b * T_SEQ + s0) * D_;
            base1 = (long)(b * T_SEQ + s1) * D_;
        }
    }

    // pipeline issue (stage = t%3): A 2x16B/thread (32B contiguous), B 800x16B
    auto issue_tile = [&](int t) {
        if (t < NITER) {
            const uint32_t st = sbase + (uint32_t)((t % NSTG) * STAGE);
            const int k0 = t * BK;
            const char* asrc = (const char*)(g_xsh +
                ((k0 < D_) ? base0 + k0 : base1 + (k0 - D_)) + half * 16);
            const uint32_t adst = st + OFF_A + arow * 80 + half * 32;
            CP16(adst,      asrc);
            CP16(adst + 16, asrc + 16);
            const char* bsrc = (const char*)g_Bpk + (size_t)t * 12800;
            const uint32_t bdst = st + OFF_B;
#pragma unroll
            for (int r = 0; r < 3; ++r) {
                int c = tid + r * NT;            // 0..767
                CP16(bdst + c * 16, bsrc + c * 16);
            }
            if (tid < 32) {
                int c = tid + 768;
                CP16(bdst + c * 16, bsrc + c * 16);
            }
        }
        CP_COMMIT();
    };

    issue_tile(0);
    issue_tile(1);

    // resident W2 (zero-padded rows >=150), b1, b2
    float* W2s = (float*)(smem + OFF_W2S);
    float* b1s = (float*)(smem + OFF_B1S);
    float* b2s = (float*)(smem + OFF_B2S);
    for (int i = tid; i < HP_ * L_; i += NT)
        W2s[i] = (i / L_ < H_) ? W2[i] : 0.f;
    if (tid < HP_) b1s[tid] = (tid < H_) ? b1[tid] : 0.f;
    if (tid < L_)  b2s[tid] = b2[tid];

    // ldmatrix lane offsets: warp owns m-tile rows [wid*16, wid*16+16)
    const uint32_t rowA = (uint32_t)((wid * 16 + (lane & 15)) * 80
                                     + (lane >> 4) * 16) + OFF_A;
    const uint32_t rowB = (uint32_t)((lane & 7) * 80 + (lane >> 3) * 16) + OFF_B;

    float acc[20][4];
#pragma unroll
    for (int j = 0; j < 20; ++j)
#pragma unroll
        for (int q = 0; q < 4; ++q) acc[j][q] = 0.f;

#pragma unroll 1
    for (int t = 0; t < NITER; ++t) {
        CP_WAIT1();
        __syncthreads();
        // stage (t+2)%3 == (t-1)%3 is dead: all warps passed the sync.
        issue_tile(t + 2);

        const uint32_t st = sbase + (uint32_t)((t % NSTG) * STAGE);
        uint32_t a[8];
        LDSM4(a[0], a[1], a[2], a[3], st + rowA);
        LDSM4(a[4], a[5], a[6], a[7], st + rowA + 32);

        const uint32_t bb = st + rowB;
#pragma unroll
        for (int j = 0; j < 20; ++j) {
            uint32_t b0, b1r, b2r, b3;
            LDSM4(b0, b1r, b2r, b3, bb + j * 640);
            MMA16816(acc[j], a[0], a[1], a[2], a[3], b0, b1r);
            MMA16816(acc[j], a[4], a[5], a[6], a[7], b2r, b3);
        }
    }

    // ---- fused epilogue in fragment domain ----
    {
        float pA[L_], pB[L_];
#pragma unroll
        for (int l = 0; l < L_; ++l) { pA[l] = 0.f; pB[l] = 0.f; }
#pragma unroll
        for (int j = 0; j < 20; ++j) {
            int c0 = 8 * j + (lane & 3) * 2;
            int c1 = c0 + 1;
            float hA0 = fmaxf(acc[j][0] + b1s[c0], 0.f);
            float hA1 = fmaxf(acc[j][1] + b1s[c1], 0.f);
            float hB0 = fmaxf(acc[j][2] + b1s[c0], 0.f);
            float hB1 = fmaxf(acc[j][3] + b1s[c1], 0.f);
            const float* w0 = W2s + c0 * L_;
            const float* w1 = W2s + c1 * L_;
#pragma unroll
            for (int l = 0; l < L_; ++l) {
                float x0 = w0[l], x1 = w1[l];
                pA[l] += hA0 * x0 + hA1 * x1;
                pB[l] += hB0 * x0 + hB1 * x1;
            }
        }
#pragma unroll
        for (int l = 0; l < L_; ++l) {
            pA[l] += __shfl_xor_sync(0xFFFFFFFF, pA[l], 1);
            pA[l] += __shfl_xor_sync(0xFFFFFFFF, pA[l], 2);
            pB[l] += __shfl_xor_sync(0xFFFFFFFF, pB[l], 1);
            pB[l] += __shfl_xor_sync(0xFFFFFFFF, pB[l], 2);
        }
        int rA = g0 + wid * 16 + (lane >> 2);
        int rB = rA + 8;
#pragma unroll
        for (int l = 0; l < L_; ++l) {
            if ((l & 3) == (lane & 3)) {   // spread stores across the quad
                if (rA < N) out[(long)rA * L_ + l] = pA[l] + b2s[l];
                if (rB < N) out[(long)rB * L_ + l] = pB[l] + b2s[l];
            }
        }
    }
}

// ---------------------------------------------------------------------------
extern "C" void kernel_launch(void* const* d_in, const int* in_sizes, int n_in,
                              void* d_out, int out_size)
{
    const float* xs    = (const float*)d_in[0];
    const int*   spans = (const int*)  d_in[1];
    const int*   bids  = (const int*)  d_in[2];
    const float* W1    = (const float*)d_in[3];
    const float* b1    = (const float*)d_in[4];
    const float* W2    = (const float*)d_in[5];
    const float* b2    = (const float*)d_in[6];
    float* out = (float*)d_out;
    const int N = in_sizes[2];

    cudaFuncSetAttribute(span_mlp_hmma4_kernel,
                         cudaFuncAttributeMaxDynamicSharedMemorySize, SMEM_TOTAL);

    prep_xs_kernel<<<(32 * 512 * 1024) / (256 * 8), 256>>>(xs);
    int w1_items = NITER * HP_ * 40;
    prep_w1_kernel<<<(w1_items + 255) / 256, 256>>>(W1);

    int grid = (N + M_CTA - 1) / M_CTA;
    span_mlp_hmma4_kernel<<<grid, NT, SMEM_TOTAL>>>(spans, bids, b1, W2, b2, out, N);
}

// round 8
// speedup vs baseline: 10.8611x; 1.8908x over previous
#include <cuda_runtime.h>
#include <cuda_fp16.h>
#include <cstdint>

// ============================================================================
// out = relu(concat(xs[b,s0], xs[b,s1]) @ W1 + b1) @ W2 + b2
//
// R8: token factorization. concat(x0,x1)@W1 = x0@W1_top + x1@W1_bot.
// Stage 1 (dense tcgen-free HMMA GEMM): uv[16384, 304] =
//          xs_fp16[16384,1024] @ [W1_top | W1_bot]_fp16   (f32 accum)
// Stage 2 (combine): per span, h = relu(u[s0] + v[s1] + b1); out = h@W2 + b2,
//          reading uv straight from L2 (19.9 MB resident).
// 4x less tensor work than span-space GEMM; A loads sequential (no gather).
// ============================================================================

#define T_SEQ 512
#define D_    1024
#define H_    150
#define L_    17
#define NTOK  16384          // 32*512
#define NCOLS 304            // 2*152 (u: cols 0..149, v: cols 152..301)
#define NHALF 152            // 19 n-tiles of 8

#define NT     256           // 8 warps
#define M_CTA  128           // tokens per CTA (1 m-tile of 16 per warp)
#define BK     32            // K per tile
#define NITER  32            // 1024/32

// stage-relative smem offsets; rows are 80B (40 halfs, k<32 valid)
#define OFF_A    0               // 128 x 80B = 10240
#define OFF_B    10240           // 152 x 80B = 12160
#define STAGE    22400
#define NSTG     3
#define SMEM_TOTAL (NSTG * STAGE)   // 67200 B

// device scratch
__device__ __align__(16) __half g_xsh[NTOK * D_];               // 32 MB
__device__ __align__(16) __half g_Bpk[NITER * NCOLS * 40];      // 778 KB
__device__ __align__(16) float  g_uv[NTOK * NCOLS];             // 19.9 MB

__device__ __forceinline__ uint32_t smem_u32(const void* p) {
    uint32_t a;
    asm("{ .reg .u64 t; cvta.to.shared.u64 t, %1; cvt.u32.u64 %0, t; }"
        : "=r"(a) : "l"(p));
    return a;
}

#define LDSM4(r0, r1, r2, r3, addr)                                          \
    asm volatile("ldmatrix.sync.aligned.m8n8.x4.shared.b16 "                 \
                 "{%0,%1,%2,%3}, [%4];"                                      \
                 : "=r"(r0), "=r"(r1), "=r"(r2), "=r"(r3) : "r"(addr))

#define MMA16816(d, a0, a1, a2, a3, b0, b1)                                  \
    asm volatile("mma.sync.aligned.m16n8k16.row.col.f32.f16.f16.f32 "        \
                 "{%0,%1,%2,%3}, {%4,%5,%6,%7}, {%8,%9}, {%0,%1,%2,%3};"     \
                 : "+f"((d)[0]), "+f"((d)[1]), "+f"((d)[2]), "+f"((d)[3])    \
                 : "r"(a0), "r"(a1), "r"(a2), "r"(a3), "r"(b0), "r"(b1))

#define CP16(dst, src)                                                        \
    asm volatile("cp.async.cg.shared.global [%0], [%1], 16;"                  \
                 :: "r"(dst), "l"(src))
#define CP_COMMIT() asm volatile("cp.async.commit_group;" ::: "memory")
#define CP_WAIT1()  asm volatile("cp.async.wait_group 1;" ::: "memory")

// ---------------------------------------------------------------------------
// Prep 1: xs f32 -> fp16 (8 floats / thread)
// ---------------------------------------------------------------------------
__global__ void prep_xs_kernel(const float* __restrict__ xs) {
    long i8 = (long)(blockIdx.x * 256 + threadIdx.x) * 8;
    float4 v0 = *(const float4*)(xs + i8);
    float4 v1 = *(const float4*)(xs + i8 + 4);
    __half2 h[4];
    h[0] = __float22half2_rn(make_float2(v0.x, v0.y));
    h[1] = __float22half2_rn(make_float2(v0.z, v0.w));
    h[2] = __float22half2_rn(make_float2(v1.x, v1.y));
    h[3] = __float22half2_rn(make_float2(v1.z, v1.w));
    *(uint4*)(g_xsh + i8) = *(uint4*)h;
}

// ---------------------------------------------------------------------------
// Prep 2: W1 [2048,150] f32 -> packed fp16 tiles [t][n(304)][kk(40)]
//   n in [0,152): W1_top col n (rows 0..1023); n in [152,304): W1_bot col n-152
// ---------------------------------------------------------------------------
__global__ void prep_w1_kernel(const float* __restrict__ W1) {
    int idx = blockIdx.x * 256 + threadIdx.x;
    if (idx >= NITER * NCOLS * 40) return;
    int t   = idx / (NCOLS * 40);
    int rem = idx - t * (NCOLS * 40);
    int n   = rem / 40;
    int kk  = rem - n * 40;
    int nh  = n / NHALF;            // 0 = top, 1 = bot
    int nl  = n - nh * NHALF;       // 0..151
    float w = 0.f;
    if (kk < BK && nl < H_)
        w = W1[(long)(nh * D_ + t * BK + kk) * H_ + nl];
    g_Bpk[idx] = __float2half_rn(w);
}

// ---------------------------------------------------------------------------
// Stage 1: token GEMM  uv[tok, nh*152 + c] = xs_fp16[tok,:] @ W1half
//   grid (128, 2): blockIdx.x = token tile, blockIdx.y = n-half
// ---------------------------------------------------------------------------
__global__ __launch_bounds__(NT, 2)
void token_gemm_kernel()
{
    extern __shared__ __align__(128) char smem[];
    const uint32_t sbase = smem_u32(smem);
    const int tid  = threadIdx.x;
    const int lane = tid & 31;
    const int wid  = tid >> 5;
    const int tok0 = blockIdx.x * M_CTA;
    const int nh   = blockIdx.y;

    // A loading: 2 threads per row (arow = tid>>1, half = tid&1, 32B each)
    const int arow = tid >> 1;
    const int half = tid & 1;
    const long abase = (long)(tok0 + arow) * D_;

    auto issue_tile = [&](int t) {
        if (t < NITER) {
            const uint32_t st = sbase + (uint32_t)((t % NSTG) * STAGE);
            const int k0 = t * BK;
            const char* asrc = (const char*)(g_xsh + abase + k0 + half * 16);
            const uint32_t adst = st + OFF_A + arow * 80 + half * 32;
            CP16(adst,      asrc);
            CP16(adst + 16, asrc + 16);
            const char* bsrc = (const char*)g_Bpk
                + ((size_t)t * NCOLS + (size_t)nh * NHALF) * 80;
            const uint32_t bdst = st + OFF_B;
#pragma unroll
            for (int r = 0; r < 3; ++r) {
                int c = tid + r * NT;            // 0..767, need < 760
                if (c < 760) CP16(bdst + c * 16, bsrc + c * 16);
            }
        }
        CP_COMMIT();
    };

    issue_tile(0);
    issue_tile(1);

    // ldmatrix lane offsets: warp owns m-tile rows [wid*16, wid*16+16)
    const uint32_t rowA = (uint32_t)((wid * 16 + (lane & 15)) * 80
                                     + (lane >> 4) * 16) + OFF_A;
    const uint32_t rowB = (uint32_t)((lane & 7) * 80 + (lane >> 3) * 16) + OFF_B;

    float acc[19][4];
#pragma unroll
    for (int j = 0; j < 19; ++j)
#pragma unroll
        for (int q = 0; q < 4; ++q) acc[j][q] = 0.f;

#pragma unroll 1
    for (int t = 0; t < NITER; ++t) {
        CP_WAIT1();
        __syncthreads();
        // stage (t+2)%3 == (t-1)%3 is dead: all warps passed the sync.
        issue_tile(t + 2);

        const uint32_t st = sbase + (uint32_t)((t % NSTG) * STAGE);
        uint32_t a[8];
        LDSM4(a[0], a[1], a[2], a[3], st + rowA);
        LDSM4(a[4], a[5], a[6], a[7], st + rowA + 32);

        const uint32_t bb = st + rowB;
#pragma unroll
        for (int j = 0; j < 19; ++j) {
            uint32_t b0, b1r, b2r, b3;
            LDSM4(b0, b1r, b2r, b3, bb + j * 640);
            MMA16816(acc[j], a[0], a[1], a[2], a[3], b0, b1r);
            MMA16816(acc[j], a[4], a[5], a[6], a[7], b2r, b3);
        }
    }

    // epilogue: write f32 fragments to g_uv
    {
        int rA = tok0 + wid * 16 + (lane >> 2);    // token row A
        float* dA = g_uv + (long)rA * NCOLS + nh * NHALF;
        float* dB = dA + 8 * NCOLS;                // row B = rA + 8
#pragma unroll
        for (int j = 0; j < 19; ++j) {
            int c0 = 8 * j + (lane & 3) * 2;
            *(float2*)(dA + c0) = make_float2(acc[j][0], acc[j][1]);
            *(float2*)(dB + c0) = make_float2(acc[j][2], acc[j][3]);
        }
    }
}

// ---------------------------------------------------------------------------
// Stage 2: combine. Thread per span: h = relu(u[s0]+v[s1]+b1); out = h@W2+b2
// ---------------------------------------------------------------------------
__global__ __launch_bounds__(256)
void combine_kernel(const int*   __restrict__ spans,
                    const int*   __restrict__ bids,
                    const float* __restrict__ b1,
                    const float* __restrict__ W2,
                    const float* __restrict__ b2,
                    float* __restrict__ out,
                    int N)
{
    __shared__ float4 W2q[38 * L_];   // [kq][l] = W2 rows 4kq..4kq+3, col l
    __shared__ float  b1s[NHALF];
    __shared__ float  b2s[L_];
    const int tid = threadIdx.x;

    for (int i = tid; i < 38 * L_; i += 256) {
        int kq = i / L_, l = i - kq * L_;
        int r = 4 * kq;
        W2q[i] = make_float4(
            (r + 0 < H_) ? W2[(r + 0) * L_ + l] : 0.f,
            (r + 1 < H_) ? W2[(r + 1) * L_ + l] : 0.f,
            (r + 2 < H_) ? W2[(r + 2) * L_ + l] : 0.f,
            (r + 3 < H_) ? W2[(r + 3) * L_ + l] : 0.f);
    }
    if (tid < NHALF) b1s[tid] = (tid < H_) ? b1[tid] : 0.f;
    if (tid < L_)    b2s[tid] = b2[tid];
    __syncthreads();

    int g = blockIdx.x * 256 + tid;
    if (g >= N) return;

    int s0 = spans[2 * g + 0];
    int s1 = spans[2 * g + 1];
    int b  = bids[g];
    const float4* pu = (const float4*)(g_uv + (long)(b * T_SEQ + s0) * NCOLS);
    const float4* pv = (const float4*)(g_uv + (long)(b * T_SEQ + s1) * NCOLS
                                       + NHALF);

    float acc[L_];
#pragma unroll
    for (int l = 0; l < L_; ++l) acc[l] = b2s[l];

#pragma unroll 2
    for (int kq = 0; kq < 38; ++kq) {
        float4 u4 = __ldg(pu + kq);
        float4 v4 = __ldg(pv + kq);
        const float4 b4 = *(const float4*)(b1s + 4 * kq);
        float h0 = fmaxf(u4.x + v4.x + b4.x, 0.f);
        float h1 = fmaxf(u4.y + v4.y + b4.y, 0.f);
        float h2 = fmaxf(u4.z + v4.z + b4.z, 0.f);
        float h3 = fmaxf(u4.w + v4.w + b4.w, 0.f);
        const float4* wq = W2q + kq * L_;
#pragma unroll
        for (int l = 0; l < L_; ++l) {
            float4 w = wq[l];
            acc[l] += h0 * w.x + h1 * w.y + h2 * w.z + h3 * w.w;
        }
    }
#pragma unroll
    for (int l = 0; l < L_; ++l) out[(long)g * L_ + l] = acc[l];
}

// ---------------------------------------------------------------------------
extern "C" void kernel_launch(void* const* d_in, const int* in_sizes, int n_in,
                              void* d_out, int out_size)
{
    const float* xs    = (const float*)d_in[0];
    const int*   spans = (const int*)  d_in[1];
    const int*   bids  = (const int*)  d_in[2];
    const float* W1    = (const float*)d_in[3];
    const float* b1    = (const float*)d_in[4];
    const float* W2    = (const float*)d_in[5];
    const float* b2    = (const float*)d_in[6];
    float* out = (float*)d_out;
    const int N = in_sizes[2];

    cudaFuncSetAttribute(token_gemm_kernel,
                         cudaFuncAttributeMaxDynamicSharedMemorySize, SMEM_TOTAL);

    prep_xs_kernel<<<(NTOK * D_) / (256 * 8), 256>>>(xs);
    int w1_items = NITER * NCOLS * 40;
    prep_w1_kernel<<<(w1_items + 255) / 256, 256>>>(W1);

    dim3 grid(NTOK / M_CTA, 2);   // (128, 2)
    token_gemm_kernel<<<grid, NT, SMEM_TOTAL>>>();

    combine_kernel<<<(N + 255) / 256, 256>>>(spans, bids, b1, W2, b2, out, N);
}

// round 9
// speedup vs baseline: 12.6660x; 1.1662x over previous
#include <cuda_runtime.h>
#include <cuda_fp16.h>
#include <cstdint>

// ============================================================================
// out = relu(concat(xs[b,s0], xs[b,s1]) @ W1 + b1) @ W2 + b2
//
// R9 = R8 (token factorization: uv[16384,304] = xs@[W1_top|W1_bot]) with:
//   - uv stored fp16 (halves combine traffic + gemm store traffic)
//   - combine kernel: 2 threads/span + shfl reduction (2x parallelism)
// ============================================================================

#define T_SEQ 512
#define D_    1024
#define H_    150
#define L_    17
#define NTOK  16384          // 32*512
#define NCOLS 304            // 2*152 (u: cols 0..149, v: cols 152..301)
#define NHALF 152            // 19 n-tiles of 8

#define NT     256           // 8 warps
#define M_CTA  128           // tokens per CTA (1 m-tile of 16 per warp)
#define BK     32            // K per tile
#define NITER  32            // 1024/32

// stage-relative smem offsets; rows are 80B (40 halfs, k<32 valid)
#define OFF_A    0               // 128 x 80B = 10240
#define OFF_B    10240           // 152 x 80B = 12160
#define STAGE    22400
#define NSTG     3
#define SMEM_TOTAL (NSTG * STAGE)   // 67200 B

// device scratch
__device__ __align__(16) __half g_xsh[NTOK * D_];               // 32 MB
__device__ __align__(16) __half g_Bpk[NITER * NCOLS * 40];      // 778 KB
__device__ __align__(16) __half g_uvh[NTOK * NCOLS];            // 9.9 MB

__device__ __forceinline__ uint32_t smem_u32(const void* p) {
    uint32_t a;
    asm("{ .reg .u64 t; cvta.to.shared.u64 t, %1; cvt.u32.u64 %0, t; }"
        : "=r"(a) : "l"(p));
    return a;
}

#define LDSM4(r0, r1, r2, r3, addr)                                          \
    asm volatile("ldmatrix.sync.aligned.m8n8.x4.shared.b16 "                 \
                 "{%0,%1,%2,%3}, [%4];"                                      \
                 : "=r"(r0), "=r"(r1), "=r"(r2), "=r"(r3) : "r"(addr))

#define MMA16816(d, a0, a1, a2, a3, b0, b1)                                  \
    asm volatile("mma.sync.aligned.m16n8k16.row.col.f32.f16.f16.f32 "        \
                 "{%0,%1,%2,%3}, {%4,%5,%6,%7}, {%8,%9}, {%0,%1,%2,%3};"     \
                 : "+f"((d)[0]), "+f"((d)[1]), "+f"((d)[2]), "+f"((d)[3])    \
                 : "r"(a0), "r"(a1), "r"(a2), "r"(a3), "r"(b0), "r"(b1))

#define CP16(dst, src)                                                        \
    asm volatile("cp.async.cg.shared.global [%0], [%1], 16;"                  \
                 :: "r"(dst), "l"(src))
#define CP_COMMIT() asm volatile("cp.async.commit_group;" ::: "memory")
#define CP_WAIT1()  asm volatile("cp.async.wait_group 1;" ::: "memory")

// ---------------------------------------------------------------------------
// Prep 1: xs f32 -> fp16 (8 floats / thread)
// ---------------------------------------------------------------------------
__global__ void prep_xs_kernel(const float* __restrict__ xs) {
    long i8 = (long)(blockIdx.x * 256 + threadIdx.x) * 8;
    float4 v0 = *(const float4*)(xs + i8);
    float4 v1 = *(const float4*)(xs + i8 + 4);
    __half2 h[4];
    h[0] = __float22half2_rn(make_float2(v0.x, v0.y));
    h[1] = __float22half2_rn(make_float2(v0.z, v0.w));
    h[2] = __float22half2_rn(make_float2(v1.x, v1.y));
    h[3] = __float22half2_rn(make_float2(v1.z, v1.w));
    *(uint4*)(g_xsh + i8) = *(uint4*)h;
}

// ---------------------------------------------------------------------------
// Prep 2: W1 [2048,150] f32 -> packed fp16 tiles [t][n(304)][kk(40)]
// ---------------------------------------------------------------------------
__global__ void prep_w1_kernel(const float* __restrict__ W1) {
    int idx = blockIdx.x * 256 + threadIdx.x;
    if (idx >= NITER * NCOLS * 40) return;
    int t   = idx / (NCOLS * 40);
    int rem = idx - t * (NCOLS * 40);
    int n   = rem / 40;
    int kk  = rem - n * 40;
    int nh  = n / NHALF;            // 0 = top, 1 = bot
    int nl  = n - nh * NHALF;       // 0..151
    float w = 0.f;
    if (kk < BK && nl < H_)
        w = W1[(long)(nh * D_ + t * BK + kk) * H_ + nl];
    g_Bpk[idx] = __float2half_rn(w);
}

// ---------------------------------------------------------------------------
// Stage 1: token GEMM  uv[tok, nh*152 + c] = xs_fp16[tok,:] @ W1half
// ---------------------------------------------------------------------------
__global__ __launch_bounds__(NT, 2)
void token_gemm_kernel()
{
    extern __shared__ __align__(128) char smem[];
    const uint32_t sbase = smem_u32(smem);
    const int tid  = threadIdx.x;
    const int lane = tid & 31;
    const int wid  = tid >> 5;
    const int tok0 = blockIdx.x * M_CTA;
    const int nh   = blockIdx.y;

    const int arow = tid >> 1;
    const int half = tid & 1;
    const long abase = (long)(tok0 + arow) * D_;

    auto issue_tile = [&](int t) {
        if (t < NITER) {
            const uint32_t st = sbase + (uint32_t)((t % NSTG) * STAGE);
            const int k0 = t * BK;
            const char* asrc = (const char*)(g_xsh + abase + k0 + half * 16);
            const uint32_t adst = st + OFF_A + arow * 80 + half * 32;
            CP16(adst,      asrc);
            CP16(adst + 16, asrc + 16);
            const char* bsrc = (const char*)g_Bpk
                + ((size_t)t * NCOLS + (size_t)nh * NHALF) * 80;
            const uint32_t bdst = st + OFF_B;
#pragma unroll
            for (int r = 0; r < 3; ++r) {
                int c = tid + r * NT;            // 0..767, need < 760
                if (c < 760) CP16(bdst + c * 16, bsrc + c * 16);
            }
        }
        CP_COMMIT();
    };

    issue_tile(0);
    issue_tile(1);

    const uint32_t rowA = (uint32_t)((wid * 16 + (lane & 15)) * 80
                                     + (lane >> 4) * 16) + OFF_A;
    const uint32_t rowB = (uint32_t)((lane & 7) * 80 + (lane >> 3) * 16) + OFF_B;

    float acc[19][4];
#pragma unroll
    for (int j = 0; j < 19; ++j)
#pragma unroll
        for (int q = 0; q < 4; ++q) acc[j][q] = 0.f;

#pragma unroll 1
    for (int t = 0; t < NITER; ++t) {
        CP_WAIT1();
        __syncthreads();
        issue_tile(t + 2);   // stage (t+2)%3 == (t-1)%3 is dead past the sync

        const uint32_t st = sbase + (uint32_t)((t % NSTG) * STAGE);
        uint32_t a[8];
        LDSM4(a[0], a[1], a[2], a[3], st + rowA);
        LDSM4(a[4], a[5], a[6], a[7], st + rowA + 32);

        const uint32_t bb = st + rowB;
#pragma unroll
        for (int j = 0; j < 19; ++j) {
            uint32_t b0, b1r, b2r, b3;
            LDSM4(b0, b1r, b2r, b3, bb + j * 640);
            MMA16816(acc[j], a[0], a[1], a[2], a[3], b0, b1r);
            MMA16816(acc[j], a[4], a[5], a[6], a[7], b2r, b3);
        }
    }

    // epilogue: pack f32 fragment pairs -> half2, store to g_uvh
    {
        int rA = tok0 + wid * 16 + (lane >> 2);
        __half* dA = g_uvh + (long)rA * NCOLS + nh * NHALF;
        __half* dB = dA + 8 * NCOLS;               // row B = rA + 8
#pragma unroll
        for (int j = 0; j < 19; ++j) {
            int c0 = 8 * j + (lane & 3) * 2;
            __half2 hA = __float22half2_rn(make_float2(acc[j][0], acc[j][1]));
            __half2 hB = __float22half2_rn(make_float2(acc[j][2], acc[j][3]));
            *(__half2*)(dA + c0) = hA;
            *(__half2*)(dB + c0) = hB;
        }
    }
}

// ---------------------------------------------------------------------------
// Stage 2: combine. 2 threads per span; each handles alternating 16B chunks
// (8 cols) of the 152 hidden; shfl-xor(1) merges the 17 partial scores.
// ---------------------------------------------------------------------------
__global__ __launch_bounds__(256)
void combine_kernel(const int*   __restrict__ spans,
                    const int*   __restrict__ bids,
                    const float* __restrict__ b1,
                    const float* __restrict__ W2,
                    const float* __restrict__ b2,
                    float* __restrict__ out,
                    int N)
{
    // W2q[q][l] = W2 rows 4q..4q+3 (col l); 38 quads cover 152 rows (zero-pad)
    __shared__ float4 W2q[38 * L_];
    __shared__ float  b1s[NHALF];
    __shared__ float  b2s[L_];
    const int tid = threadIdx.x;

    for (int i = tid; i < 38 * L_; i += 256) {
        int q = i / L_, l = i - q * L_;
        int r = 4 * q;
        W2q[i] = make_float4(
            (r + 0 < H_) ? W2[(r + 0) * L_ + l] : 0.f,
            (r + 1 < H_) ? W2[(r + 1) * L_ + l] : 0.f,
            (r + 2 < H_) ? W2[(r + 2) * L_ + l] : 0.f,
            (r + 3 < H_) ? W2[(r + 3) * L_ + l] : 0.f);
    }
    if (tid < NHALF) b1s[tid] = (tid < H_) ? b1[tid] : 0.f;
    if (tid < L_)    b2s[tid] = b2[tid];
    __syncthreads();

    const int gid  = blockIdx.x * 256 + tid;
    const int g    = gid >> 1;        // span
    const int part = gid & 1;         // which half of the chunks
    if (g >= N) return;

    int s0 = spans[2 * g + 0];
    int s1 = spans[2 * g + 1];
    int b  = bids[g];
    const uint4* pu = (const uint4*)(g_uvh + (long)(b * T_SEQ + s0) * NCOLS);
    const uint4* pv = (const uint4*)(g_uvh + (long)(b * T_SEQ + s1) * NCOLS
                                     + NHALF);

    float acc[L_];
#pragma unroll
    for (int l = 0; l < L_; ++l) acc[l] = 0.f;

    // 19 uint4 chunks (8 cols each); this thread takes chunks part, part+2,...
#pragma unroll
    for (int it = 0; it < 10; ++it) {
        int c8 = part + it * 2;          // chunk index
        if (c8 >= 19) break;
        uint4 uu = __ldg(pu + c8);
        uint4 vv = __ldg(pv + c8);
        const __half2* uh = (const __half2*)&uu;
        const __half2* vh = (const __half2*)&vv;
        int cbase = c8 * 8;
#pragma unroll
        for (int q = 0; q < 4; ++q) {
            float2 uf = __half22float2(uh[q]);
            float2 vf = __half22float2(vh[q]);
            int c = cbase + q * 2;
            float h0 = fmaxf(uf.x + vf.x + b1s[c],     0.f);
            float h1 = fmaxf(uf.y + vf.y + b1s[c + 1], 0.f);
            // W2 rows c, c+1 live in quad (c>>2), components (c&3), (c&3)+1
            const float4* wq = W2q + (c >> 2) * L_;
            if ((c & 3) == 0) {
#pragma unroll
                for (int l = 0; l < L_; ++l) {
                    float4 w = wq[l];
                    acc[l] += h0 * w.x + h1 * w.y;
                }
            } else {
#pragma unroll
                for (int l = 0; l < L_; ++l) {
                    float4 w = wq[l];
                    acc[l] += h0 * w.z + h1 * w.w;
                }
            }
        }
    }

    // merge the two partials (threads gid, gid^1 share a span)
#pragma unroll
    for (int l = 0; l < L_; ++l)
        acc[l] += __shfl_xor_sync(0xFFFFFFFF, acc[l], 1);

    // split the 17 stores across the pair
    float* po = out + (long)g * L_;
#pragma unroll
    for (int l = 0; l < L_; ++l)
        if ((l & 1) == part) po[l] = acc[l] + b2s[l];
}

// ---------------------------------------------------------------------------
extern "C" void kernel_launch(void* const* d_in, const int* in_sizes, int n_in,
                              void* d_out, int out_size)
{
    const float* xs    = (const float*)d_in[0];
    const int*   spans = (const int*)  d_in[1];
    const int*   bids  = (const int*)  d_in[2];
    const float* W1    = (const float*)d_in[3];
    const float* b1    = (const float*)d_in[4];
    const float* W2    = (const float*)d_in[5];
    const float* b2    = (const float*)d_in[6];
    float* out = (float*)d_out;
    const int N = in_sizes[2];

    cudaFuncSetAttribute(token_gemm_kernel,
                         cudaFuncAttributeMaxDynamicSharedMemorySize, SMEM_TOTAL);

    prep_xs_kernel<<<(NTOK * D_) / (256 * 8), 256>>>(xs);
    int w1_items = NITER * NCOLS * 40;
    prep_w1_kernel<<<(w1_items + 255) / 256, 256>>>(W1);

    dim3 grid(NTOK / M_CTA, 2);   // (128, 2)
    token_gemm_kernel<<<grid, NT, SMEM_TOTAL>>>();

    combine_kernel<<<(2 * N + 255) / 256, 256>>>(spans, bids, b1, W2, b2, out, N);
}

// round 10
// speedup vs baseline: 13.1739x; 1.0401x over previous
#include <cuda_runtime.h>
#include <cuda_fp16.h>
#include <cstdint>

// ============================================================================
// out = relu(concat(xs[b,s0], xs[b,s1]) @ W1 + b1) @ W2 + b2
//
// R10 = R9 (token factorization, fp16 uv) with:
//   - prep_xs eliminated: fp32->fp16 A conversion fused into token_gemm
//     (register-staged LDG/cvt/STS overlapped with the MMA mainloop)
//   - combine: each thread handles 2 spans (halves W2 LDS per span, 2x ILP)
// ============================================================================

#define T_SEQ 512
#define D_    1024
#define H_    150
#define L_    17
#define NTOK  16384          // 32*512
#define NCOLS 304            // u: cols 0..149 (of 152), v: cols 152..301
#define NHALF 152            // 19 n-tiles of 8

#define NT     256           // 8 warps
#define M_CTA  128           // tokens per CTA (1 m-tile of 16 per warp)
#define BK     32            // K per tile
#define NITER  32            // 1024/32

// stage-relative smem offsets; rows are 80B (40 halfs, k<32 valid)
#define OFF_A    0               // 128 x 80B = 10240
#define OFF_B    10240           // 152 x 80B = 12160
#define STAGE    22400
#define NSTG     3
#define SMEM_TOTAL (NSTG * STAGE)   // 67200 B

// device scratch
__device__ __align__(16) __half g_Bpk[NITER * NCOLS * 40];      // 778 KB
__device__ __align__(16) __half g_uvh[NTOK * NCOLS];            // 9.9 MB

__device__ __forceinline__ uint32_t smem_u32(const void* p) {
    uint32_t a;
    asm("{ .reg .u64 t; cvta.to.shared.u64 t, %1; cvt.u32.u64 %0, t; }"
        : "=r"(a) : "l"(p));
    return a;
}

#define LDSM4(r0, r1, r2, r3, addr)                                          \
    asm volatile("ldmatrix.sync.aligned.m8n8.x4.shared.b16 "                 \
                 "{%0,%1,%2,%3}, [%4];"                                      \
                 : "=r"(r0), "=r"(r1), "=r"(r2), "=r"(r3) : "r"(addr))

#define MMA16816(d, a0, a1, a2, a3, b0, b1)                                  \
    asm volatile("mma.sync.aligned.m16n8k16.row.col.f32.f16.f16.f32 "        \
                 "{%0,%1,%2,%3}, {%4,%5,%6,%7}, {%8,%9}, {%0,%1,%2,%3};"     \
                 : "+f"((d)[0]), "+f"((d)[1]), "+f"((d)[2]), "+f"((d)[3])    \
                 : "r"(a0), "r"(a1), "r"(a2), "r"(a3), "r"(b0), "r"(b1))

#define CP16(dst, src)                                                        \
    asm volatile("cp.async.cg.shared.global [%0], [%1], 16;"                  \
                 :: "r"(dst), "l"(src))
#define CP_COMMIT() asm volatile("cp.async.commit_group;" ::: "memory")
#define CP_WAIT1()  asm volatile("cp.async.wait_group 1;" ::: "memory")

// ---------------------------------------------------------------------------
// Prep: W1 [2048,150] f32 -> packed fp16 tiles [t][n(304)][kk(40)]
// ---------------------------------------------------------------------------
__global__ void prep_w1_kernel(const float* __restrict__ W1) {
    int idx = blockIdx.x * 256 + threadIdx.x;
    if (idx >= NITER * NCOLS * 40) return;
    int t   = idx / (NCOLS * 40);
    int rem = idx - t * (NCOLS * 40);
    int n   = rem / 40;
    int kk  = rem - n * 40;
    int nh  = n / NHALF;            // 0 = top, 1 = bot
    int nl  = n - nh * NHALF;       // 0..151
    float w = 0.f;
    if (kk < BK && nl < H_)
        w = W1[(long)(nh * D_ + t * BK + kk) * H_ + nl];
    g_Bpk[idx] = __float2half_rn(w);
}

// ---------------------------------------------------------------------------
// Stage 1: token GEMM  uv[tok, nh*152 + c] = fp16(xs[tok,:]) @ W1half
//   A converted in-kernel: LDG fp32 -> cvt -> STS fp16 (overlapped w/ MMA).
// ---------------------------------------------------------------------------
__global__ __launch_bounds__(NT, 2)
void token_gemm_kernel(const float* __restrict__ xs)
{
    extern __shared__ __align__(128) char smem[];
    const uint32_t sbase = smem_u32(smem);
    const int tid  = threadIdx.x;
    const int lane = tid & 31;
    const int wid  = tid >> 5;
    const int tok0 = blockIdx.x * M_CTA;
    const int nh   = blockIdx.y;

    const int arow = tid >> 1;
    const int half = tid & 1;
    const float* asrc_base = xs + (long)(tok0 + arow) * D_ + half * 16;

    // A: load 16 fp32 of tile t, convert to 8 half2 in regs
    auto ldgA = [&](int t, uint32_t rh[8]) {
        if (t < NITER) {
            const float4* src = (const float4*)(asrc_base + t * BK);
#pragma unroll
            for (int i = 0; i < 4; ++i) {
                float4 v = __ldg(src + i);
                __half2 h0 = __float22half2_rn(make_float2(v.x, v.y));
                __half2 h1 = __float22half2_rn(make_float2(v.z, v.w));
                rh[i * 2]     = *(uint32_t*)&h0;
                rh[i * 2 + 1] = *(uint32_t*)&h1;
            }
        }
    };
    auto stsA = [&](int t, const uint32_t rh[8]) {
        if (t < NITER) {
            char* adst = smem + (t % NSTG) * STAGE + OFF_A
                       + arow * 80 + half * 32;
            *(uint4*)adst        = make_uint4(rh[0], rh[1], rh[2], rh[3]);
            *(uint4*)(adst + 16) = make_uint4(rh[4], rh[5], rh[6], rh[7]);
        }
    };
    // B: cp.async 760x16B
    auto issueB = [&](int t) {
        if (t < NITER) {
            const uint32_t st = sbase + (uint32_t)((t % NSTG) * STAGE);
            const char* bsrc = (const char*)g_Bpk
                + ((size_t)t * NCOLS + (size_t)nh * NHALF) * 80;
            const uint32_t bdst = st + OFF_B;
#pragma unroll
            for (int r = 0; r < 3; ++r) {
                int c = tid + r * NT;            // 0..767, need < 760
                if (c < 760) CP16(bdst + c * 16, bsrc + c * 16);
            }
        }
        CP_COMMIT();
    };

    // prologue: A(0) staged, A(1) in regs, B(0), B(1) in flight
    uint32_t ra[8];
    ldgA(0, ra);
    issueB(0);
    stsA(0, ra);
    ldgA(1, ra);
    issueB(1);

    const uint32_t rowA = (uint32_t)((wid * 16 + (lane & 15)) * 80
                                     + (lane >> 4) * 16) + OFF_A;
    const uint32_t rowB = (uint32_t)((lane & 7) * 80 + (lane >> 3) * 16) + OFF_B;

    float acc[19][4];
#pragma unroll
    for (int j = 0; j < 19; ++j)
#pragma unroll
        for (int q = 0; q < 4; ++q) acc[j][q] = 0.f;

#pragma unroll 1
    for (int t = 0; t < NITER; ++t) {
        CP_WAIT1();
        __syncthreads();
        issueB(t + 2);       // stage (t+2)%3 B region is dead past the sync
        stsA(t + 1, ra);     // A(t+1): stage (t+1)%3 A region last read 2 syncs ago
        ldgA(t + 2, ra);     // prefetch next

        const uint32_t st = sbase + (uint32_t)((t % NSTG) * STAGE);
        uint32_t a[8];
        LDSM4(a[0], a[1], a[2], a[3], st + rowA);
        LDSM4(a[4], a[5], a[6], a[7], st + rowA + 32);

        const uint32_t bb = st + rowB;
#pragma unroll
        for (int j = 0; j < 19; ++j) {
            uint32_t b0, b1r, b2r, b3;
            LDSM4(b0, b1r, b2r, b3, bb + j * 640);
            MMA16816(acc[j], a[0], a[1], a[2], a[3], b0, b1r);
            MMA16816(acc[j], a[4], a[5], a[6], a[7], b2r, b3);
        }
    }

    // epilogue: pack f32 fragment pairs -> half2, store to g_uvh
    {
        int rA = tok0 + wid * 16 + (lane >> 2);
        __half* dA = g_uvh + (long)rA * NCOLS + nh * NHALF;
        __half* dB = dA + 8 * NCOLS;               // row B = rA + 8
#pragma unroll
        for (int j = 0; j < 19; ++j) {
            int c0 = 8 * j + (lane & 3) * 2;
            __half2 hA = __float22half2_rn(make_float2(acc[j][0], acc[j][1]));
            __half2 hB = __float22half2_rn(make_float2(acc[j][2], acc[j][3]));
            *(__half2*)(dA + c0) = hA;
            *(__half2*)(dB + c0) = hB;
        }
    }
}

// ---------------------------------------------------------------------------
// Stage 2: combine. Each thread: 2 spans x one part (alternating 16B chunks);
// W2 quad LDS amortized over both spans; shfl-xor(1) merges partner part.
// ---------------------------------------------------------------------------
__global__ __launch_bounds__(256)
void combine_kernel(const int*   __restrict__ spans,
                    const int*   __restrict__ bids,
                    const float* __restrict__ b1,
                    const float* __restrict__ W2,
                    const float* __restrict__ b2,
                    float* __restrict__ out,
                    int N)
{
    // W2q[q][l] = W2 rows 4q..4q+3 (col l); 38 quads cover 152 rows (zero-pad)
    __shared__ float4 W2q[38 * L_];
    __shared__ float  b1s[NHALF];
    __shared__ float  b2s[L_];
    const int tid = threadIdx.x;

    for (int i = tid; i < 38 * L_; i += 256) {
        int q = i / L_, l = i - q * L_;
        int r = 4 * q;
        W2q[i] = make_float4(
            (r + 0 < H_) ? W2[(r + 0) * L_ + l] : 0.f,
            (r + 1 < H_) ? W2[(r + 1) * L_ + l] : 0.f,
            (r + 2 < H_) ? W2[(r + 2) * L_ + l] : 0.f,
            (r + 3 < H_) ? W2[(r + 3) * L_ + l] : 0.f);
    }
    if (tid < NHALF) b1s[tid] = (tid < H_) ? b1[tid] : 0.f;
    if (tid < L_)    b2s[tid] = b2[tid];
    __syncthreads();

    const int gid  = blockIdx.x * 256 + tid;
    const int part = gid & 1;         // which half of the chunks
    const int ga   = (gid >> 1) * 2;  // first span of the pair
    if (ga >= N) return;
    const bool two = (ga + 1 < N);
    const int gb   = two ? ga + 1 : ga;

    int s0a = spans[2 * ga], s1a = spans[2 * ga + 1], ba = bids[ga];
    int s0b = spans[2 * gb], s1b = spans[2 * gb + 1], bb = bids[gb];
    const uint4* pu0 = (const uint4*)(g_uvh + (long)(ba * T_SEQ + s0a) * NCOLS);
    const uint4* pv0 = (const uint4*)(g_uvh + (long)(ba * T_SEQ + s1a) * NCOLS + NHALF);
    const uint4* pu1 = (const uint4*)(g_uvh + (long)(bb * T_SEQ + s0b) * NCOLS);
    const uint4* pv1 = (const uint4*)(g_uvh + (long)(bb * T_SEQ + s1b) * NCOLS + NHALF);

    float acc0[L_], acc1[L_];
#pragma unroll
    for (int l = 0; l < L_; ++l) { acc0[l] = 0.f; acc1[l] = 0.f; }

#pragma unroll
    for (int it = 0; it < 10; ++it) {
        int c8 = part + it * 2;          // chunk index (8 cols)
        if (c8 >= 19) break;
        uint4 u0 = __ldg(pu0 + c8);
        uint4 v0 = __ldg(pv0 + c8);
        uint4 u1 = __ldg(pu1 + c8);
        uint4 v1 = __ldg(pv1 + c8);
        const __half2* uh0 = (const __half2*)&u0;
        const __half2* vh0 = (const __half2*)&v0;
        const __half2* uh1 = (const __half2*)&u1;
        const __half2* vh1 = (const __half2*)&v1;
        int cbase = c8 * 8;
#pragma unroll
        for (int q = 0; q < 4; ++q) {
            int c = cbase + q * 2;
            float2 a0 = __half22float2(uh0[q]);
            float2 c0v = __half22float2(vh0[q]);
            float2 a1 = __half22float2(uh1[q]);
            float2 c1v = __half22float2(vh1[q]);
            float b1c0 = b1s[c], b1c1 = b1s[c + 1];
            float h00 = fmaxf(a0.x + c0v.x + b1c0, 0.f);
            float h01 = fmaxf(a0.y + c0v.y + b1c1, 0.f);
            float h10 = fmaxf(a1.x + c1v.x + b1c0, 0.f);
            float h11 = fmaxf(a1.y + c1v.y + b1c1, 0.f);
            const float4* wq = W2q + (c >> 2) * L_;
            if ((c & 3) == 0) {
#pragma unroll
                for (int l = 0; l < L_; ++l) {
                    float4 w = wq[l];
                    acc0[l] += h00 * w.x + h01 * w.y;
                    acc1[l] += h10 * w.x + h11 * w.y;
                }
            } else {
#pragma unroll
                for (int l = 0; l < L_; ++l) {
                    float4 w = wq[l];
                    acc0[l] += h00 * w.z + h01 * w.w;
                    acc1[l] += h10 * w.z + h11 * w.w;
                }
            }
        }
    }

    // merge the two parts (threads gid, gid^1 share the span pair)
#pragma unroll
    for (int l = 0; l < L_; ++l) {
        acc0[l] += __shfl_xor_sync(0xFFFFFFFF, acc0[l], 1);
        acc1[l] += __shfl_xor_sync(0xFFFFFFFF, acc1[l], 1);
    }

    float* poA = out + (long)ga * L_;
    float* poB = out + (long)gb * L_;
#pragma unroll
    for (int l = 0; l < L_; ++l) {
        if ((l & 1) == part) {
            poA[l] = acc0[l] + b2s[l];
            if (two) poB[l] = acc1[l] + b2s[l];
        }
    }
}

// ---------------------------------------------------------------------------
extern "C" void kernel_launch(void* const* d_in, const int* in_sizes, int n_in,
                              void* d_out, int out_size)
{
    const float* xs    = (const float*)d_in[0];
    const int*   spans = (const int*)  d_in[1];
    const int*   bids  = (const int*)  d_in[2];
    const float* W1    = (const float*)d_in[3];
    const float* b1    = (const float*)d_in[4];
    const float* W2    = (const float*)d_in[5];
    const float* b2    = (const float*)d_in[6];
    float* out = (float*)d_out;
    const int N = in_sizes[2];

    cudaFuncSetAttribute(token_gemm_kernel,
                         cudaFuncAttributeMaxDynamicSharedMemorySize, SMEM_TOTAL);

    int w1_items = NITER * NCOLS * 40;
    prep_w1_kernel<<<(w1_items + 255) / 256, 256>>>(W1);

    dim3 grid(NTOK / M_CTA, 2);   // (128, 2)
    token_gemm_kernel<<<grid, NT, SMEM_TOTAL>>>(xs);

    combine_kernel<<<(N + 255) / 256, 256>>>(spans, bids, b1, W2, b2, out, N);
}

// round 11
// speedup vs baseline: 14.2027x; 1.0781x over previous
#include <cuda_runtime.h>
#include <cuda_fp16.h>
#include <cstdint>

// ============================================================================
// out = relu(concat(xs[b,s0], xs[b,s1]) @ W1 + b1) @ W2 + b2
//
// R11 = R10 with token_gemm restructured: one 512-thread CTA computes BOTH
// n-halves sharing a single A tile (xs read once from DRAM, A-path work
// amortized over 2x the MMAs). grid=(128,1): one clean wave.
// ============================================================================

#define T_SEQ 512
#define D_    1024
#define H_    150
#define L_    17
#define NTOK  16384          // 32*512
#define NCOLS 304            // u: cols 0..149 (of 152), v: cols 152..301
#define NHALF 152            // 19 n-tiles of 8

#define NT     512           // 16 warps: 8 per n-half
#define M_CTA  128           // tokens per CTA (m-tile of 16 per warp, x8)
#define BK     32            // K per tile
#define NITER  32            // 1024/32

// stage-relative smem offsets; rows are 80B (40 halfs, k<32 valid)
#define OFF_A    0               // 128 x 80B = 10240
#define OFF_B    10240           // 304 x 80B = 24320
#define STAGE    34560
#define NSTG     3
#define SMEM_TOTAL (NSTG * STAGE)   // 103680 B

// device scratch
__device__ __align__(16) __half g_Bpk[NITER * NCOLS * 40];      // 778 KB
__device__ __align__(16) __half g_uvh[NTOK * NCOLS];            // 9.9 MB

__device__ __forceinline__ uint32_t smem_u32(const void* p) {
    uint32_t a;
    asm("{ .reg .u64 t; cvta.to.shared.u64 t, %1; cvt.u32.u64 %0, t; }"
        : "=r"(a) : "l"(p));
    return a;
}

#define LDSM4(r0, r1, r2, r3, addr)                                          \
    asm volatile("ldmatrix.sync.aligned.m8n8.x4.shared.b16 "                 \
                 "{%0,%1,%2,%3}, [%4];"                                      \
                 : "=r"(r0), "=r"(r1), "=r"(r2), "=r"(r3) : "r"(addr))

#define MMA16816(d, a0, a1, a2, a3, b0, b1)                                  \
    asm volatile("mma.sync.aligned.m16n8k16.row.col.f32.f16.f16.f32 "        \
                 "{%0,%1,%2,%3}, {%4,%5,%6,%7}, {%8,%9}, {%0,%1,%2,%3};"     \
                 : "+f"((d)[0]), "+f"((d)[1]), "+f"((d)[2]), "+f"((d)[3])    \
                 : "r"(a0), "r"(a1), "r"(a2), "r"(a3), "r"(b0), "r"(b1))

#define CP16(dst, src)                                                        \
    asm volatile("cp.async.cg.shared.global [%0], [%1], 16;"                  \
                 :: "r"(dst), "l"(src))
#define CP_COMMIT() asm volatile("cp.async.commit_group;" ::: "memory")
#define CP_WAIT1()  asm volatile("cp.async.wait_group 1;" ::: "memory")

// ---------------------------------------------------------------------------
// Prep: W1 [2048,150] f32 -> packed fp16 tiles [t][n(304)][kk(40)]
// ---------------------------------------------------------------------------
__global__ void prep_w1_kernel(const float* __restrict__ W1) {
    int idx = blockIdx.x * 256 + threadIdx.x;
    if (idx >= NITER * NCOLS * 40) return;
    int t   = idx / (NCOLS * 40);
    int rem = idx - t * (NCOLS * 40);
    int n   = rem / 40;
    int kk  = rem - n * 40;
    int nh  = n / NHALF;            // 0 = top, 1 = bot
    int nl  = n - nh * NHALF;       // 0..151
    float w = 0.f;
    if (kk < BK && nl < H_)
        w = W1[(long)(nh * D_ + t * BK + kk) * H_ + nl];
    g_Bpk[idx] = __float2half_rn(w);
}

// ---------------------------------------------------------------------------
// Stage 1: token GEMM  uv[tok, :304] = fp16(xs[tok,:]) @ [W1_top | W1_bot]
//   16 warps: warp w computes m-tile (w&7), n-half (w>>3); A tile shared.
// ---------------------------------------------------------------------------
__global__ __launch_bounds__(NT, 1)
void token_gemm_kernel(const float* __restrict__ xs)
{
    extern __shared__ __align__(128) char smem[];
    const uint32_t sbase = smem_u32(smem);
    const int tid  = threadIdx.x;
    const int lane = tid & 31;
    const int wid  = tid >> 5;
    const int mt   = wid & 7;       // m-tile 0..7
    const int nh   = wid >> 3;      // n-half 0/1
    const int tok0 = blockIdx.x * M_CTA;

    // A: 4 threads per row; each loads 8 fp32 (32B) -> 8 half (16B)
    const int arow  = tid >> 2;     // 0..127
    const int aquad = tid & 3;      // which 8-col group
    const float* asrc_base = xs + (long)(tok0 + arow) * D_ + aquad * 8;

    auto ldgA = [&](int t, uint32_t rh[4]) {
        if (t < NITER) {
            const float4* src = (const float4*)(asrc_base + t * BK);
            float4 v0 = __ldg(src);
            float4 v1 = __ldg(src + 1);
            __half2 h0 = __float22half2_rn(make_float2(v0.x, v0.y));
            __half2 h1 = __float22half2_rn(make_float2(v0.z, v0.w));
            __half2 h2 = __float22half2_rn(make_float2(v1.x, v1.y));
            __half2 h3 = __float22half2_rn(make_float2(v1.z, v1.w));
            rh[0] = *(uint32_t*)&h0; rh[1] = *(uint32_t*)&h1;
            rh[2] = *(uint32_t*)&h2; rh[3] = *(uint32_t*)&h3;
        }
    };
    auto stsA = [&](int t, const uint32_t rh[4]) {
        if (t < NITER) {
            char* adst = smem + (t % NSTG) * STAGE + OFF_A
                       + arow * 80 + aquad * 16;
            *(uint4*)adst = make_uint4(rh[0], rh[1], rh[2], rh[3]);
        }
    };
    // B: cp.async 1520x16B (both halves, contiguous in g_Bpk)
    auto issueB = [&](int t) {
        if (t < NITER) {
            const uint32_t st = sbase + (uint32_t)((t % NSTG) * STAGE);
            const char* bsrc = (const char*)g_Bpk + (size_t)t * (NCOLS * 80);
            const uint32_t bdst = st + OFF_B;
#pragma unroll
            for (int r = 0; r < 3; ++r) {
                int c = tid + r * NT;            // 0..1535, need < 1520
                if (c < 1520) CP16(bdst + c * 16, bsrc + c * 16);
            }
        }
        CP_COMMIT();
    };

    // prologue
    uint32_t ra[4];
    ldgA(0, ra);
    issueB(0);
    stsA(0, ra);
    ldgA(1, ra);
    issueB(1);

    const uint32_t rowA = (uint32_t)((mt * 16 + (lane & 15)) * 80
                                     + (lane >> 4) * 16) + OFF_A;
    const uint32_t rowB = (uint32_t)(nh * (NHALF * 80)
                                     + (lane & 7) * 80 + (lane >> 3) * 16) + OFF_B;

    float acc[19][4];
#pragma unroll
    for (int j = 0; j < 19; ++j)
#pragma unroll
        for (int q = 0; q < 4; ++q) acc[j][q] = 0.f;

#pragma unroll 1
    for (int t = 0; t < NITER; ++t) {
        CP_WAIT1();
        __syncthreads();
        issueB(t + 2);       // stage (t+2)%3 B region dead past the sync
        stsA(t + 1, ra);     // stage (t+1)%3 A region last read 2 syncs ago
        ldgA(t + 2, ra);     // prefetch next

        const uint32_t st = sbase + (uint32_t)((t % NSTG) * STAGE);
        uint32_t a[8];
        LDSM4(a[0], a[1], a[2], a[3], st + rowA);
        LDSM4(a[4], a[5], a[6], a[7], st + rowA + 32);

        const uint32_t bb = st + rowB;
#pragma unroll
        for (int j = 0; j < 19; ++j) {
            uint32_t b0, b1r, b2r, b3;
            LDSM4(b0, b1r, b2r, b3, bb + j * 640);
            MMA16816(acc[j], a[0], a[1], a[2], a[3], b0, b1r);
            MMA16816(acc[j], a[4], a[5], a[6], a[7], b2r, b3);
        }
    }

    // epilogue: pack f32 fragment pairs -> half2, store to g_uvh
    {
        int rA = tok0 + mt * 16 + (lane >> 2);
        __half* dA = g_uvh + (long)rA * NCOLS + nh * NHALF;
        __half* dB = dA + 8 * NCOLS;               // row B = rA + 8
#pragma unroll
        for (int j = 0; j < 19; ++j) {
            int c0 = 8 * j + (lane & 3) * 2;
            __half2 hA = __float22half2_rn(make_float2(acc[j][0], acc[j][1]));
            __half2 hB = __float22half2_rn(make_float2(acc[j][2], acc[j][3]));
            *(__half2*)(dA + c0) = hA;
            *(__half2*)(dB + c0) = hB;
        }
    }
}

// ---------------------------------------------------------------------------
// Stage 2: combine. Each thread: 2 spans x one part (alternating 16B chunks);
// W2 quad LDS amortized over both spans; shfl-xor(1) merges partner part.
// ---------------------------------------------------------------------------
__global__ __launch_bounds__(256)
void combine_kernel(const int*   __restrict__ spans,
                    const int*   __restrict__ bids,
                    const float* __restrict__ b1,
                    const float* __restrict__ W2,
                    const float* __restrict__ b2,
                    float* __restrict__ out,
                    int N)
{
    // W2q[q][l] = W2 rows 4q..4q+3 (col l); 38 quads cover 152 rows (zero-pad)
    __shared__ float4 W2q[38 * L_];
    __shared__ float  b1s[NHALF];
    __shared__ float  b2s[L_];
    const int tid = threadIdx.x;

    for (int i = tid; i < 38 * L_; i += 256) {
        int q = i / L_, l = i - q * L_;
        int r = 4 * q;
        W2q[i] = make_float4(
            (r + 0 < H_) ? W2[(r + 0) * L_ + l] : 0.f,
            (r + 1 < H_) ? W2[(r + 1) * L_ + l] : 0.f,
            (r + 2 < H_) ? W2[(r + 2) * L_ + l] : 0.f,
            (r + 3 < H_) ? W2[(r + 3) * L_ + l] : 0.f);
    }
    if (tid < NHALF) b1s[tid] = (tid < H_) ? b1[tid] : 0.f;
    if (tid < L_)    b2s[tid] = b2[tid];
    __syncthreads();

    const int gid  = blockIdx.x * 256 + tid;
    const int part = gid & 1;         // which half of the chunks
    const int ga   = (gid >> 1) * 2;  // first span of the pair
    if (ga >= N) return;
    const bool two = (ga + 1 < N);
    const int gb   = two ? ga + 1 : ga;

    int s0a = spans[2 * ga], s1a = spans[2 * ga + 1], ba = bids[ga];
    int s0b = spans[2 * gb], s1b = spans[2 * gb + 1], bb = bids[gb];
    const uint4* pu0 = (const uint4*)(g_uvh + (long)(ba * T_SEQ + s0a) * NCOLS);
    const uint4* pv0 = (const uint4*)(g_uvh + (long)(ba * T_SEQ + s1a) * NCOLS + NHALF);
    const uint4* pu1 = (const uint4*)(g_uvh + (long)(bb * T_SEQ + s0b) * NCOLS);
    const uint4* pv1 = (const uint4*)(g_uvh + (long)(bb * T_SEQ + s1b) * NCOLS + NHALF);

    float acc0[L_], acc1[L_];
#pragma unroll
    for (int l = 0; l < L_; ++l) { acc0[l] = 0.f; acc1[l] = 0.f; }

#pragma unroll
    for (int it = 0; it < 10; ++it) {
        int c8 = part + it * 2;          // chunk index (8 cols)
        if (c8 >= 19) break;
        uint4 u0 = __ldg(pu0 + c8);
        uint4 v0 = __ldg(pv0 + c8);
        uint4 u1 = __ldg(pu1 + c8);
        uint4 v1 = __ldg(pv1 + c8);
        const __half2* uh0 = (const __half2*)&u0;
        const __half2* vh0 = (const __half2*)&v0;
        const __half2* uh1 = (const __half2*)&u1;
        const __half2* vh1 = (const __half2*)&v1;
        int cbase = c8 * 8;
#pragma unroll
        for (int q = 0; q < 4; ++q) {
            int c = cbase + q * 2;
            float2 a0 = __half22float2(uh0[q]);
            float2 c0v = __half22float2(vh0[q]);
            float2 a1 = __half22float2(uh1[q]);
            float2 c1v = __half22float2(vh1[q]);
            float b1c0 = b1s[c], b1c1 = b1s[c + 1];
            float h00 = fmaxf(a0.x + c0v.x + b1c0, 0.f);
            float h01 = fmaxf(a0.y + c0v.y + b1c1, 0.f);
            float h10 = fmaxf(a1.x + c1v.x + b1c0, 0.f);
            float h11 = fmaxf(a1.y + c1v.y + b1c1, 0.f);
            const float4* wq = W2q + (c >> 2) * L_;
            if ((c & 3) == 0) {
#pragma unroll
                for (int l = 0; l < L_; ++l) {
                    float4 w = wq[l];
                    acc0[l] += h00 * w.x + h01 * w.y;
                    acc1[l] += h10 * w.x + h11 * w.y;
                }
            } else {
#pragma unroll
                for (int l = 0; l < L_; ++l) {
                    float4 w = wq[l];
                    acc0[l] += h00 * w.z + h01 * w.w;
                    acc1[l] += h10 * w.z + h11 * w.w;
                }
            }
        }
    }

#pragma unroll
    for (int l = 0; l < L_; ++l) {
        acc0[l] += __shfl_xor_sync(0xFFFFFFFF, acc0[l], 1);
        acc1[l] += __shfl_xor_sync(0xFFFFFFFF, acc1[l], 1);
    }

    float* poA = out + (long)ga * L_;
    float* poB = out + (long)gb * L_;
#pragma unroll
    for (int l = 0; l < L_; ++l) {
        if ((l & 1) == part) {
            poA[l] = acc0[l] + b2s[l];
            if (two) poB[l] = acc1[l] + b2s[l];
        }
    }
}

// ---------------------------------------------------------------------------
extern "C" void kernel_launch(void* const* d_in, const int* in_sizes, int n_in,
                              void* d_out, int out_size)
{
    const float* xs    = (const float*)d_in[0];
    const int*   spans = (const int*)  d_in[1];
    const int*   bids  = (const int*)  d_in[2];
    const float* W1    = (const float*)d_in[3];
    const float* b1    = (const float*)d_in[4];
    const float* W2    = (const float*)d_in[5];
    const float* b2    = (const float*)d_in[6];
    float* out = (float*)d_out;
    const int N = in_sizes[2];

    cudaFuncSetAttribute(token_gemm_kernel,
                         cudaFuncAttributeMaxDynamicSharedMemorySize, SMEM_TOTAL);

    int w1_items = NITER * NCOLS * 40;
    prep_w1_kernel<<<(w1_items + 255) / 256, 256>>>(W1);

    token_gemm_kernel<<<NTOK / M_CTA, NT, SMEM_TOTAL>>>(xs);

    combine_kernel<<<(N + 255) / 256, 256>>>(spans, bids, b1, W2, b2, out, N);
}

// round 12
// speedup vs baseline: 15.5777x; 1.0968x over previous
#include <cuda_runtime.h>
#include <cuda_fp16.h>
#include <cstdint>

// ============================================================================
// out = relu(concat(xs[b,s0], xs[b,s1]) @ W1 + b1) @ W2 + b2
//
// R12 = R11 with BK 32->64 in token_gemm (16 K-tiles instead of 32: half the
// barriers/commits/loop-head stalls), rows padded to 144B (conflict-free
// LDSM), per-tile K processed in two halves to cap registers. prep_w1
// vectorized (uint4 stores). Combine unchanged.
// ============================================================================

#define T_SEQ 512
#define D_    1024
#define H_    150
#define L_    17
#define NTOK  16384          // 32*512
#define NCOLS 304            // u: cols 0..149 (of 152), v: cols 152..301
#define NHALF 152            // 19 n-tiles of 8

#define NT     512           // 16 warps: 8 m-tiles x 2 n-halves
#define M_CTA  128           // tokens per CTA
#define BK     64            // K per tile
#define NITER  16            // 1024/64

// rows are 144B (72 halfs: 64 valid + 8 pad)
#define ROWB     144
#define OFF_A    0                         // 128 x 144 = 18432
#define OFF_B    18432                     // 304 x 144 = 43776
#define STAGE    62208
#define NSTG     3
#define SMEM_TOTAL (NSTG * STAGE)          // 186624 B

// device scratch
__device__ __align__(16) __half g_Bpk[NITER * NCOLS * 72];      // 700 KB
__device__ __align__(16) __half g_uvh[NTOK * NCOLS];            // 9.9 MB

__device__ __forceinline__ uint32_t smem_u32(const void* p) {
    uint32_t a;
    asm("{ .reg .u64 t; cvta.to.shared.u64 t, %1; cvt.u32.u64 %0, t; }"
        : "=r"(a) : "l"(p));
    return a;
}

#define LDSM4(r0, r1, r2, r3, addr)                                          \
    asm volatile("ldmatrix.sync.aligned.m8n8.x4.shared.b16 "                 \
                 "{%0,%1,%2,%3}, [%4];"                                      \
                 : "=r"(r0), "=r"(r1), "=r"(r2), "=r"(r3) : "r"(addr))

#define MMA16816(d, a0, a1, a2, a3, b0, b1)                                  \
    asm volatile("mma.sync.aligned.m16n8k16.row.col.f32.f16.f16.f32 "        \
                 "{%0,%1,%2,%3}, {%4,%5,%6,%7}, {%8,%9}, {%0,%1,%2,%3};"     \
                 : "+f"((d)[0]), "+f"((d)[1]), "+f"((d)[2]), "+f"((d)[3])    \
                 : "r"(a0), "r"(a1), "r"(a2), "r"(a3), "r"(b0), "r"(b1))

#define CP16(dst, src)                                                        \
    asm volatile("cp.async.cg.shared.global [%0], [%1], 16;"                  \
                 :: "r"(dst), "l"(src))
#define CP_COMMIT() asm volatile("cp.async.commit_group;" ::: "memory")
#define CP_WAIT1()  asm volatile("cp.async.wait_group 1;" ::: "memory")

// ---------------------------------------------------------------------------
// Prep: W1 [2048,150] f32 -> packed fp16 tiles [t(16)][n(304)][72 halfs]
//   (kk<64 & nl<150 valid, else 0). One uint4 (8 halfs) per thread.
// ---------------------------------------------------------------------------
__global__ void prep_w1_kernel(const float* __restrict__ W1) {
    int idx = blockIdx.x * 256 + threadIdx.x;   // (t, n, kq), kq in 0..8
    if (idx >= NITER * NCOLS * 9) return;
    int t   = idx / (NCOLS * 9);
    int rem = idx - t * (NCOLS * 9);
    int n   = rem / 9;
    int kq  = rem - n * 9;
    int nh  = n / NHALF;
    int nl  = n - nh * NHALF;
    __half h[8];
#pragma unroll
    for (int i = 0; i < 8; ++i) {
        int kk = kq * 8 + i;
        float w = 0.f;
        if (kq < 8 && nl < H_)
            w = W1[(long)(nh * D_ + t * BK + kk) * H_ + nl];
        h[i] = __float2half_rn(w);
    }
    *(uint4*)(g_Bpk + ((size_t)t * NCOLS + n) * 72 + kq * 8) = *(uint4*)h;
}

// ---------------------------------------------------------------------------
// Stage 1: token GEMM  uv[tok, :304] = fp16(xs[tok,:]) @ [W1_top | W1_bot]
//   16 warps: warp w -> m-tile (w&7), n-half (w>>3); A tile shared.
// ---------------------------------------------------------------------------
__global__ __launch_bounds__(NT, 1)
void token_gemm_kernel(const float* __restrict__ xs)
{
    extern __shared__ __align__(128) char smem[];
    const uint32_t sbase = smem_u32(smem);
    const int tid  = threadIdx.x;
    const int lane = tid & 31;
    const int wid  = tid >> 5;
    const int mt   = wid & 7;       // m-tile 0..7
    const int nh   = wid >> 3;      // n-half 0/1
    const int tok0 = blockIdx.x * M_CTA;

    // A: 4 threads per row; each loads 16 fp32 (64B) -> 16 half (32B)
    const int arow  = tid >> 2;     // 0..127
    const int aquad = tid & 3;      // 16-col group within the 64-k tile
    const float* asrc_base = xs + (long)(tok0 + arow) * D_ + aquad * 16;

    auto ldgA = [&](int t, uint32_t rh[8]) {
        if (t < NITER) {
            const float4* src = (const float4*)(asrc_base + t * BK);
#pragma unroll
            for (int i = 0; i < 4; ++i) {
                float4 v = __ldg(src + i);
                __half2 h0 = __float22half2_rn(make_float2(v.x, v.y));
                __half2 h1 = __float22half2_rn(make_float2(v.z, v.w));
                rh[i * 2]     = *(uint32_t*)&h0;
                rh[i * 2 + 1] = *(uint32_t*)&h1;
            }
        }
    };
    auto stsA = [&](int t, const uint32_t rh[8]) {
        if (t < NITER) {
            char* adst = smem + (t % NSTG) * STAGE + OFF_A
                       + arow * ROWB + aquad * 32;
            *(uint4*)adst        = make_uint4(rh[0], rh[1], rh[2], rh[3]);
            *(uint4*)(adst + 16) = make_uint4(rh[4], rh[5], rh[6], rh[7]);
        }
    };
    // B: cp.async 2736x16B (both halves, contiguous per tile in g_Bpk)
    auto issueB = [&](int t) {
        if (t < NITER) {
            const uint32_t st = sbase + (uint32_t)((t % NSTG) * STAGE);
            const char* bsrc = (const char*)g_Bpk + (size_t)t * (NCOLS * ROWB);
            const uint32_t bdst = st + OFF_B;
#pragma unroll
            for (int r = 0; r < 6; ++r) {
                int c = tid + r * NT;            // 0..3071, need < 2736
                if (c < 2736) CP16(bdst + c * 16, bsrc + c * 16);
            }
        }
        CP_COMMIT();
    };

    // prologue
    uint32_t ra[8];
    ldgA(0, ra);
    issueB(0);
    stsA(0, ra);
    ldgA(1, ra);
    issueB(1);

    const uint32_t rowA = (uint32_t)((mt * 16 + (lane & 15)) * ROWB
                                     + (lane >> 4) * 16) + OFF_A;
    const uint32_t rowB = (uint32_t)(nh * (NHALF * ROWB)
                                     + (lane & 7) * ROWB + (lane >> 3) * 16) + OFF_B;

    float acc[19][4];
#pragma unroll
    for (int j = 0; j < 19; ++j)
#pragma unroll
        for (int q = 0; q < 4; ++q) acc[j][q] = 0.f;

#pragma unroll 1
    for (int t = 0; t < NITER; ++t) {
        CP_WAIT1();
        __syncthreads();
        issueB(t + 2);       // stage (t+2)%3 B region dead past the sync
        stsA(t + 1, ra);     // stage (t+1)%3 A region last read 2 syncs ago
        ldgA(t + 2, ra);     // prefetch next

        const uint32_t st = sbase + (uint32_t)((t % NSTG) * STAGE);
        const uint32_t aa = st + rowA;
        const uint32_t bb = st + rowB;

        // ---- K-half 0 (k 0..31) ----
        {
            uint32_t a[8];
            LDSM4(a[0], a[1], a[2], a[3], aa);
            LDSM4(a[4], a[5], a[6], a[7], aa + 32);
#pragma unroll
            for (int j = 0; j < 19; ++j) {
                uint32_t b0, b1r, b2r, b3;
                LDSM4(b0, b1r, b2r, b3, bb + j * (8 * ROWB));
                MMA16816(acc[j], a[0], a[1], a[2], a[3], b0, b1r);
                MMA16816(acc[j], a[4], a[5], a[6], a[7], b2r, b3);
            }
        }
        // ---- K-half 1 (k 32..63) ----
        {
            uint32_t a[8];
            LDSM4(a[0], a[1], a[2], a[3], aa + 64);
            LDSM4(a[4], a[5], a[6], a[7], aa + 96);
#pragma unroll
            for (int j = 0; j < 19; ++j) {
                uint32_t b0, b1r, b2r, b3;
                LDSM4(b0, b1r, b2r, b3, bb + j * (8 * ROWB) + 64);
                MMA16816(acc[j], a[0], a[1], a[2], a[3], b0, b1r);
                MMA16816(acc[j], a[4], a[5], a[6], a[7], b2r, b3);
            }
        }
    }

    // epilogue: pack f32 fragment pairs -> half2, store to g_uvh
    {
        int rA = tok0 + mt * 16 + (lane >> 2);
        __half* dA = g_uvh + (long)rA * NCOLS + nh * NHALF;
        __half* dB = dA + 8 * NCOLS;               // row B = rA + 8
#pragma unroll
        for (int j = 0; j < 19; ++j) {
            int c0 = 8 * j + (lane & 3) * 2;
            __half2 hA = __float22half2_rn(make_float2(acc[j][0], acc[j][1]));
            __half2 hB = __float22half2_rn(make_float2(acc[j][2], acc[j][3]));
            *(__half2*)(dA + c0) = hA;
            *(__half2*)(dB + c0) = hB;
        }
    }
}

// ---------------------------------------------------------------------------
// Stage 2: combine. Each thread: 2 spans x one part (alternating 16B chunks);
// W2 quad LDS amortized over both spans; shfl-xor(1) merges partner part.
// ---------------------------------------------------------------------------
__global__ __launch_bounds__(256)
void combine_kernel(const int*   __restrict__ spans,
                    const int*   __restrict__ bids,
                    const float* __restrict__ b1,
                    const float* __restrict__ W2,
                    const float* __restrict__ b2,
                    float* __restrict__ out,
                    int N)
{
    __shared__ float4 W2q[38 * L_];
    __shared__ float  b1s[NHALF];
    __shared__ float  b2s[L_];
    const int tid = threadIdx.x;

    for (int i = tid; i < 38 * L_; i += 256) {
        int q = i / L_, l = i - q * L_;
        int r = 4 * q;
        W2q[i] = make_float4(
            (r + 0 < H_) ? W2[(r + 0) * L_ + l] : 0.f,
            (r + 1 < H_) ? W2[(r + 1) * L_ + l] : 0.f,
            (r + 2 < H_) ? W2[(r + 2) * L_ + l] : 0.f,
            (r + 3 < H_) ? W2[(r + 3) * L_ + l] : 0.f);
    }
    if (tid < NHALF) b1s[tid] = (tid < H_) ? b1[tid] : 0.f;
    if (tid < L_)    b2s[tid] = b2[tid];
    __syncthreads();

    const int gid  = blockIdx.x * 256 + tid;
    const int part = gid & 1;
    const int ga   = (gid >> 1) * 2;
    if (ga >= N) return;
    const bool two = (ga + 1 < N);
    const int gb   = two ? ga + 1 : ga;

    int s0a = spans[2 * ga], s1a = spans[2 * ga + 1], ba = bids[ga];
    int s0b = spans[2 * gb], s1b = spans[2 * gb + 1], bb = bids[gb];
    const uint4* pu0 = (const uint4*)(g_uvh + (long)(ba * T_SEQ + s0a) * NCOLS);
    const uint4* pv0 = (const uint4*)(g_uvh + (long)(ba * T_SEQ + s1a) * NCOLS + NHALF);
    const uint4* pu1 = (const uint4*)(g_uvh + (long)(bb * T_SEQ + s0b) * NCOLS);
    const uint4* pv1 = (const uint4*)(g_uvh + (long)(bb * T_SEQ + s1b) * NCOLS + NHALF);

    float acc0[L_], acc1[L_];
#pragma unroll
    for (int l = 0; l < L_; ++l) { acc0[l] = 0.f; acc1[l] = 0.f; }

#pragma unroll
    for (int it = 0; it < 10; ++it) {
        int c8 = part + it * 2;
        if (c8 >= 19) break;
        uint4 u0 = __ldg(pu0 + c8);
        uint4 v0 = __ldg(pv0 + c8);
        uint4 u1 = __ldg(pu1 + c8);
        uint4 v1 = __ldg(pv1 + c8);
        const __half2* uh0 = (const __half2*)&u0;
        const __half2* vh0 = (const __half2*)&v0;
        const __half2* uh1 = (const __half2*)&u1;
        const __half2* vh1 = (const __half2*)&v1;
        int cbase = c8 * 8;
#pragma unroll
        for (int q = 0; q < 4; ++q) {
            int c = cbase + q * 2;
            float2 a0 = __half22float2(uh0[q]);
            float2 c0v = __half22float2(vh0[q]);
            float2 a1 = __half22float2(uh1[q]);
            float2 c1v = __half22float2(vh1[q]);
            float b1c0 = b1s[c], b1c1 = b1s[c + 1];
            float h00 = fmaxf(a0.x + c0v.x + b1c0, 0.f);
            float h01 = fmaxf(a0.y + c0v.y + b1c1, 0.f);
            float h10 = fmaxf(a1.x + c1v.x + b1c0, 0.f);
            float h11 = fmaxf(a1.y + c1v.y + b1c1, 0.f);
            const float4* wq = W2q + (c >> 2) * L_;
            if ((c & 3) == 0) {
#pragma unroll
                for (int l = 0; l < L_; ++l) {
                    float4 w = wq[l];
                    acc0[l] += h00 * w.x + h01 * w.y;
                    acc1[l] += h10 * w.x + h11 * w.y;
                }
            } else {
#pragma unroll
                for (int l = 0; l < L_; ++l) {
                    float4 w = wq[l];
                    acc0[l] += h00 * w.z + h01 * w.w;
                    acc1[l] += h10 * w.z + h11 * w.w;
                }
            }
        }
    }

#pragma unroll
    for (int l = 0; l < L_; ++l) {
        acc0[l] += __shfl_xor_sync(0xFFFFFFFF, acc0[l], 1);
        acc1[l] += __shfl_xor_sync(0xFFFFFFFF, acc1[l], 1);
    }

    float* poA = out + (long)ga * L_;
    float* poB = out + (long)gb * L_;
#pragma unroll
    for (int l = 0; l < L_; ++l) {
        if ((l & 1) == part) {
            poA[l] = acc0[l] + b2s[l];
            if (two) poB[l] = acc1[l] + b2s[l];
        }
    }
}

// ---------------------------------------------------------------------------
extern "C" void kernel_launch(void* const* d_in, const int* in_sizes, int n_in,
                              void* d_out, int out_size)
{
    const float* xs    = (const float*)d_in[0];
    const int*   spans = (const int*)  d_in[1];
    const int*   bids  = (const int*)  d_in[2];
    const float* W1    = (const float*)d_in[3];
    const float* b1    = (const float*)d_in[4];
    const float* W2    = (const float*)d_in[5];
    const float* b2    = (const float*)d_in[6];
    float* out = (float*)d_out;
    const int N = in_sizes[2];

    cudaFuncSetAttribute(token_gemm_kernel,
                         cudaFuncAttributeMaxDynamicSharedMemorySize, SMEM_TOTAL);

    int w1_items = NITER * NCOLS * 9;
    prep_w1_kernel<<<(w1_items + 255) / 256, 256>>>(W1);

    token_gemm_kernel<<<NTOK / M_CTA, NT, SMEM_TOTAL>>>(xs);

    combine_kernel<<<(N + 255) / 256, 256>>>(spans, bids, b1, W2, b2, out, N);
}